// round 9
// baseline (speedup 1.0000x reference)
#include <cuda_runtime.h>
#include <cuda_fp16.h>
#include <cstdint>
#include <math.h>

// ---------------- problem constants ----------------
#define Bq    4
#define LIN   13294
#define MTOK  (Bq * LIN)      // 53176
#define DMODEL 256
#define NHEAD 8
#define NLVL  4
#define NPTS  4
#define DH    32
#define DFF   1024

// ---------------- scratch (device globals) ----------------
__device__ float  g_q    [(size_t)MTOK * DMODEL];
__device__ __half g_qh   [(size_t)MTOK * DMODEL];
__device__ __half g_value[(size_t)MTOK * DMODEL];   // TRANSPOSED: [head][tok][32]
__device__ float  g_offs [(size_t)MTOK * DMODEL];   // reused for ff2 out
__device__ float  g_aw   [(size_t)MTOK * 128];      // raw logits
__device__ __half g_msdah[(size_t)MTOK * DMODEL];
__device__ float  g_src2 [(size_t)MTOK * DMODEL];
__device__ float  g_x    [(size_t)MTOK * DMODEL];
__device__ __half g_xh   [(size_t)MTOK * DMODEL];
__device__ __half g_ffh  [(size_t)MTOK * DFF];
// weights: Wt[N, K] fp16 K-major
__device__ __half g_wt_proj[640 * 256];
__device__ __half g_wt_out [256 * 256];
__device__ __half g_wt_ff1 [1024 * 256];
__device__ __half g_wt_ff2 [256 * 1024];
__device__ float  g_bias_proj[640];

// ---------------- helpers ----------------
__device__ __forceinline__ uint32_t smem_u32(const void* p) {
    uint32_t a;
    asm("{ .reg .u64 t; cvta.to.shared.u64 t, %1; cvt.u32.u64 %0, t; }" : "=r"(a) : "l"(p));
    return a;
}
#define CP_ASYNC16(dst, src) \
    asm volatile("cp.async.cg.shared.global [%0], [%1], 16;\n" :: "r"(dst), "l"(src) : "memory")
#define CP_COMMIT() asm volatile("cp.async.commit_group;\n" ::: "memory")
#define CP_WAIT(n)  asm volatile("cp.async.wait_group %0;\n" :: "n"(n) : "memory")

__device__ __forceinline__ void ldmatrix_x4(uint32_t& r0, uint32_t& r1, uint32_t& r2, uint32_t& r3, uint32_t addr) {
    asm volatile("ldmatrix.sync.aligned.m8n8.x4.shared.b16 {%0,%1,%2,%3}, [%4];"
                 : "=r"(r0), "=r"(r1), "=r"(r2), "=r"(r3) : "r"(addr));
}
__device__ __forceinline__ void mma_f16(float* c, const uint32_t* a, const uint32_t* b) {
    asm volatile("mma.sync.aligned.m16n8k16.row.col.f32.f16.f16.f32 "
                 "{%0,%1,%2,%3}, {%4,%5,%6,%7}, {%8,%9}, {%0,%1,%2,%3};"
                 : "+f"(c[0]), "+f"(c[1]), "+f"(c[2]), "+f"(c[3])
                 : "r"(a[0]), "r"(a[1]), "r"(a[2]), "r"(a[3]), "r"(b[0]), "r"(b[1]));
}

// ---------------- fp16 warp-MMA GEMM, 4-stage cp.async pipeline ------------
// mode 0: Cf fp32 [M,N]. mode 1: Ch fp16 [M,N].
// mode 2: cols 0-255 -> Ch TRANSPOSED value layout [head][tok][32];
//         cols 256-511 -> C2 (fp32, stride 256); 512-639 -> C3 (fp32, 128).
#define PADS 40
#define STAGE_ELEMS (128 * PADS)
#define NSTAGE 4
#define GEMM_SMEM (2 * NSTAGE * STAGE_ELEMS * 2)   // 81920 bytes

__global__ __launch_bounds__(256, 2)
void gemm_mma(const __half* __restrict__ A, int lda,
              const __half* __restrict__ B, int ldb,
              const float* __restrict__ bias,
              float* __restrict__ Cf, __half* __restrict__ Ch,
              float* __restrict__ C2, float* __restrict__ C3,
              int M, int K, int N, int relu, int mode)
{
    extern __shared__ __align__(16) __half dynsmem[];

    const int tid  = threadIdx.x;
    const int wid  = tid >> 5;
    const int lane = tid & 31;
    const int wm   = wid & 3;
    const int wn   = wid >> 2;
    const int row0 = blockIdx.y * 128;
    const int col0 = blockIdx.x * 128;

    const uint32_t sbase = smem_u32(dynsmem);
    const int NC = K >> 5;

    float acc[2][8][4];
#pragma unroll
    for (int i = 0; i < 2; i++)
#pragma unroll
        for (int j = 0; j < 8; j++)
#pragma unroll
            for (int t = 0; t < 4; t++) acc[i][j][t] = 0.f;

#define LOAD_STAGE(buf, cc) do {                                              \
        int _kc = (cc) << 5;                                                  \
        uint32_t _dA = sbase + (buf) * (STAGE_ELEMS * 2);                     \
        uint32_t _dB = sbase + (NSTAGE + (buf)) * (STAGE_ELEMS * 2);          \
        _Pragma("unroll")                                                     \
        for (int _i = 0; _i < 2; ++_i) {                                      \
            int _c = tid + _i * 256;                                          \
            int _r = _c >> 2, _k8 = _c & 3;                                   \
            int _gr = row0 + _r; if (_gr >= M) _gr = M - 1;                   \
            CP_ASYNC16(_dA + (_r * PADS + _k8 * 8) * 2,                       \
                       A + (size_t)_gr * lda + _kc + _k8 * 8);                \
        }                                                                     \
        _Pragma("unroll")                                                     \
        for (int _i = 0; _i < 2; ++_i) {                                      \
            int _c = tid + _i * 256;                                          \
            int _r = _c >> 2, _k8 = _c & 3;                                   \
            CP_ASYNC16(_dB + (_r * PADS + _k8 * 8) * 2,                       \
                       B + (size_t)(col0 + _r) * ldb + _kc + _k8 * 8);        \
        }                                                                     \
    } while (0)

    LOAD_STAGE(0, 0); CP_COMMIT();
    LOAD_STAGE(1, 1); CP_COMMIT();
    LOAD_STAGE(2, 2); CP_COMMIT();

    for (int c = 0; c < NC; ++c) {
        const int buf = c & 3;
        CP_WAIT(2);
        __syncthreads();

        if (c + 3 < NC) LOAD_STAGE((c + 3) & 3, c + 3);
        CP_COMMIT();

        const uint32_t baseA = sbase + buf * (STAGE_ELEMS * 2);
        const uint32_t baseB = sbase + (NSTAGE + buf) * (STAGE_ELEMS * 2);

#pragma unroll
        for (int kk = 0; kk < 32; kk += 16) {
            uint32_t a[2][4];
#pragma unroll
            for (int mt = 0; mt < 2; mt++) {
                int r = wm * 32 + mt * 16 + (lane & 15);
                int kc = kk + ((lane & 16) ? 8 : 0);
                ldmatrix_x4(a[mt][0], a[mt][1], a[mt][2], a[mt][3],
                            baseA + (r * PADS + kc) * 2);
            }
            uint32_t b[8][2];
#pragma unroll
            for (int np = 0; np < 4; np++) {
                int n = wn * 64 + np * 16 + (lane & 7) + ((lane & 16) ? 8 : 0);
                int kc = kk + ((lane & 8) ? 8 : 0);
                ldmatrix_x4(b[2 * np][0], b[2 * np][1], b[2 * np + 1][0], b[2 * np + 1][1],
                            baseB + (n * PADS + kc) * 2);
            }
#pragma unroll
            for (int mt = 0; mt < 2; mt++)
#pragma unroll
                for (int nt = 0; nt < 8; nt++)
                    mma_f16(acc[mt][nt], a[mt], b[nt]);
        }
        __syncthreads();
    }

    // ---- epilogue ----
    // write_kind: 0 = fp32 row-major, 1 = fp16 row-major, 2 = fp16 transposed value
    float* outf = Cf;
    __half* outh = Ch;
    int ostride = N, coff = 0;
    int write_kind = (mode == 1) ? 1 : 0;
    if (mode == 2) {
        if (col0 < 256)      { outh = Ch; write_kind = 2; }
        else if (col0 < 512) { outf = C2; ostride = 256; coff = 256; }
        else                 { outf = C3; ostride = 128; coff = 512; }
    }

#pragma unroll
    for (int mt = 0; mt < 2; mt++) {
#pragma unroll
        for (int half_i = 0; half_i < 2; half_i++) {
            int r = row0 + wm * 32 + mt * 16 + (lane >> 2) + half_i * 8;
            if (r >= M) continue;
#pragma unroll
            for (int nt = 0; nt < 8; nt++) {
                int cidx = col0 + wn * 64 + nt * 8 + (lane & 3) * 2;
                float v0 = acc[mt][nt][half_i * 2 + 0] + bias[cidx];
                float v1 = acc[mt][nt][half_i * 2 + 1] + bias[cidx + 1];
                if (relu) { v0 = fmaxf(v0, 0.f); v1 = fmaxf(v1, 0.f); }
                if (write_kind == 2) {
                    __half2 hv;
                    hv.x = __float2half_rn(v0);
                    hv.y = __float2half_rn(v1);
                    size_t addr = ((size_t)(cidx >> 5) * MTOK + r) * 32 + (cidx & 31);
                    *reinterpret_cast<__half2*>(outh + addr) = hv;
                } else if (write_kind == 1) {
                    __half2 hv;
                    hv.x = __float2half_rn(v0);
                    hv.y = __float2half_rn(v1);
                    *reinterpret_cast<__half2*>(outh + (size_t)r * ostride + cidx) = hv;
                } else {
                    float2 o = make_float2(v0, v1);
                    *reinterpret_cast<float2*>(outf + (size_t)r * ostride + (cidx - coff)) = o;
                }
            }
        }
    }
#undef LOAD_STAGE
}

// ---------------- fused weight prep + q = src + pos ------------------------
__device__ __forceinline__ void wtr1(const float* __restrict__ W, __half* __restrict__ Wt,
                                     int K_, int N_, int i)
{
    int k = i / N_, n = i % N_;
    Wt[(size_t)n * K_ + k] = __float2half_rn(W[i]);
}

#define PREP_ITEMS 754304
#define ADD_ITEMS  (MTOK * DMODEL / 4)
#define PA_TOTAL   (PREP_ITEMS + ADD_ITEMS)

__global__ void prep_add_kernel(const float* __restrict__ vW, const float* __restrict__ oW,
                                const float* __restrict__ aW, const float* __restrict__ uW,
                                const float* __restrict__ f1W, const float* __restrict__ f2W,
                                const float* __restrict__ vb, const float* __restrict__ ob,
                                const float* __restrict__ ab,
                                __half* __restrict__ wtp, __half* __restrict__ wtu,
                                __half* __restrict__ wtf1, __half* __restrict__ wtf2,
                                float* __restrict__ biasp,
                                const float* __restrict__ srca, const float* __restrict__ posb,
                                float* __restrict__ q, __half* __restrict__ qh)
{
    int i = blockIdx.x * blockDim.x + threadIdx.x;
    if (i >= PREP_ITEMS) {
        // q = src + pos, float4
        int t = i - PREP_ITEMS;
        if (t >= ADD_ITEMS) return;
        float4 x = reinterpret_cast<const float4*>(srca)[t];
        float4 y = reinterpret_cast<const float4*>(posb)[t];
        x.x += y.x; x.y += y.y; x.z += y.z; x.w += y.w;
        reinterpret_cast<float4*>(q)[t] = x;
        __half2 h0 = __floats2half2_rn(x.x, x.y);
        __half2 h1 = __floats2half2_rn(x.z, x.w);
        uint2 hp;
        hp.x = *reinterpret_cast<uint32_t*>(&h0);
        hp.y = *reinterpret_cast<uint32_t*>(&h1);
        reinterpret_cast<uint2*>(qh)[t] = hp;
        return;
    }
    if (i < 65536)       { wtr1(vW, wtp, 256, 256, i); return; }
    i -= 65536;
    if (i < 65536)       { wtr1(oW, wtp + 256 * 256, 256, 256, i); return; }
    i -= 65536;
    if (i < 32768)       { wtr1(aW, wtp + 512 * 256, 256, 128, i); return; }
    i -= 32768;
    if (i < 65536)       { wtr1(uW, wtu, 256, 256, i); return; }
    i -= 65536;
    if (i < 262144)      { wtr1(f1W, wtf1, 256, 1024, i); return; }
    i -= 262144;
    if (i < 262144)      { wtr1(f2W, wtf2, 1024, 256, i); return; }
    i -= 262144;
    if (i < 256)         { biasp[i] = vb[i]; return; }
    if (i < 512)         { biasp[i] = ob[i - 256]; return; }
    if (i < 640)         { biasp[i] = ab[i - 512]; return; }
}

// ---------------- MSDA: fused softmax + float4 gathers, transposed value ---
// value layout: [head][MTOK][32 ch]. Corner x-pairs are 64B-adjacent.
__global__ __launch_bounds__(256)
void msda_kernel(const __half* __restrict__ value, const float* __restrict__ offs,
                 const float* __restrict__ aw, const float* __restrict__ ref,
                 const int* __restrict__ shapes, const int* __restrict__ starts,
                 __half* __restrict__ outh)
{
    const int tok = blockIdx.x;
    const int h = threadIdx.x >> 5;
    const int lane = threadIdx.x & 31;
    const int j = lane & 15;
    const int b = tok / LIN;
    const int l = j >> 2;

    // ---- per-point precompute (duplicated in both 16-lane halves) ----
    const int Hl = shapes[l * 2 + 0];
    const int Wl = shapes[l * 2 + 1];
    const int st = starts[l];
    const float fW = (float)Wl, fH = (float)Hl;
    const float rx = ref[(size_t)tok * 8 + l * 2 + 0];
    const float ry = ref[(size_t)tok * 8 + l * 2 + 1];
    const float2 off = *reinterpret_cast<const float2*>(offs + (size_t)tok * 256 + h * 32 + 2 * j);

    float logit = aw[(size_t)tok * 128 + h * 16 + j];
    float m = logit;
#pragma unroll
    for (int o = 8; o; o >>= 1) m = fmaxf(m, __shfl_xor_sync(0xffffffffu, m, o, 16));
    float e = expf(logit - m);
    float s = e;
#pragma unroll
    for (int o = 8; o; o >>= 1) s += __shfl_xor_sync(0xffffffffu, s, o, 16);
    float wgt = e / s;

    float x = (rx + off.x / fW) * fW - 0.5f;
    float y = (ry + off.y / fH) * fH - 0.5f;
    float x0f = floorf(x), y0f = floorf(y);
    float dx = x - x0f, dy = y - y0f;
    int x0 = (int)x0f, y0 = (int)y0f;
    int x1 = x0 + 1, y1 = y0 + 1;

    bool xv0 = (x0 >= 0) & (x0 < Wl);
    bool xv1 = (x1 >= 0) & (x1 < Wl);
    bool yv0 = (y0 >= 0) & (y0 < Hl);
    bool yv1 = (y1 >= 0) & (y1 < Hl);

    float w00 = (xv0 && yv0) ? wgt * (1.f - dx) * (1.f - dy) : 0.f;
    float w10 = (xv1 && yv0) ? wgt * dx * (1.f - dy) : 0.f;
    float w01 = (xv0 && yv1) ? wgt * (1.f - dx) * dy : 0.f;
    float w11 = (xv1 && yv1) ? wgt * dx * dy : 0.f;

    int cx0 = min(max(x0, 0), Wl - 1), cx1 = min(max(x1, 0), Wl - 1);
    int cy0 = min(max(y0, 0), Hl - 1), cy1 = min(max(y1, 0), Hl - 1);
    const int base = b * LIN + st;
    int i00 = base + cy0 * Wl + cx0;
    int i10 = base + cy0 * Wl + cx1;
    int i01 = base + cy1 * Wl + cx0;
    int i11 = base + cy1 * Wl + cx1;

    // ---- gather: 2 passes x 8 points, float4 (8 channels) per lane ----
    const int g = lane >> 2;
    const int c4 = lane & 3;
    const __half* vch = value + (size_t)h * MTOK * 32 + c4 * 8;
    float acc[8] = {0.f, 0.f, 0.f, 0.f, 0.f, 0.f, 0.f, 0.f};

#pragma unroll
    for (int p = 0; p < 2; p++) {
        const int pt = p * 8 + g;
        int a00 = __shfl_sync(0xffffffffu, i00, pt);
        int a10 = __shfl_sync(0xffffffffu, i10, pt);
        int a01 = __shfl_sync(0xffffffffu, i01, pt);
        int a11 = __shfl_sync(0xffffffffu, i11, pt);
        float u00 = __shfl_sync(0xffffffffu, w00, pt);
        float u10 = __shfl_sync(0xffffffffu, w10, pt);
        float u01 = __shfl_sync(0xffffffffu, w01, pt);
        float u11 = __shfl_sync(0xffffffffu, w11, pt);

        uint4 r00 = *reinterpret_cast<const uint4*>(vch + (size_t)a00 * 32);
        uint4 r10 = *reinterpret_cast<const uint4*>(vch + (size_t)a10 * 32);
        uint4 r01 = *reinterpret_cast<const uint4*>(vch + (size_t)a01 * 32);
        uint4 r11 = *reinterpret_cast<const uint4*>(vch + (size_t)a11 * 32);

#define ACC8(rv, u) do {                                                      \
        const __half2* _h = reinterpret_cast<const __half2*>(&(rv));          \
        _Pragma("unroll")                                                     \
        for (int _k = 0; _k < 4; _k++) {                                      \
            float2 _f = __half22float2(_h[_k]);                               \
            acc[2 * _k + 0] = fmaf(u, _f.x, acc[2 * _k + 0]);                 \
            acc[2 * _k + 1] = fmaf(u, _f.y, acc[2 * _k + 1]);                 \
        } } while (0)

        ACC8(r00, u00);
        ACC8(r10, u10);
        ACC8(r01, u01);
        ACC8(r11, u11);
#undef ACC8
    }

    // ---- reduce over the 8 point-groups ----
#pragma unroll
    for (int o = 4; o <= 16; o <<= 1) {
#pragma unroll
        for (int k = 0; k < 8; k++)
            acc[k] += __shfl_xor_sync(0xffffffffu, acc[k], o);
    }

    if (lane < 4) {
        __half2 h0 = __floats2half2_rn(acc[0], acc[1]);
        __half2 h1 = __floats2half2_rn(acc[2], acc[3]);
        __half2 h2 = __floats2half2_rn(acc[4], acc[5]);
        __half2 h3 = __floats2half2_rn(acc[6], acc[7]);
        uint4 o;
        o.x = *reinterpret_cast<uint32_t*>(&h0);
        o.y = *reinterpret_cast<uint32_t*>(&h1);
        o.z = *reinterpret_cast<uint32_t*>(&h2);
        o.w = *reinterpret_cast<uint32_t*>(&h3);
        *reinterpret_cast<uint4*>(outh + (size_t)tok * DMODEL + h * DH + lane * 8) = o;
    }
}

// ---------------- warp-per-token residual add + LayerNorm ------------------
__global__ __launch_bounds__(256)
void add_ln_kernel(const float* __restrict__ a, const float* __restrict__ r,
                   const float* __restrict__ g, const float* __restrict__ bb,
                   float* __restrict__ out, __half* __restrict__ outh)
{
    const int tok = (blockIdx.x * blockDim.x + threadIdx.x) >> 5;
    const int lane = threadIdx.x & 31;
    if (tok >= MTOK) return;

    const float4* a4 = reinterpret_cast<const float4*>(a + (size_t)tok * DMODEL);
    const float4* r4 = reinterpret_cast<const float4*>(r + (size_t)tok * DMODEL);
    float4 v0 = a4[lane * 2 + 0], v1 = a4[lane * 2 + 1];
    float4 u0 = r4[lane * 2 + 0], u1 = r4[lane * 2 + 1];
    v0.x += u0.x; v0.y += u0.y; v0.z += u0.z; v0.w += u0.w;
    v1.x += u1.x; v1.y += u1.y; v1.z += u1.z; v1.w += u1.w;

    float s = v0.x + v0.y + v0.z + v0.w + v1.x + v1.y + v1.z + v1.w;
#pragma unroll
    for (int o = 16; o; o >>= 1) s += __shfl_xor_sync(0xffffffffu, s, o);
    float mean = s * (1.f / 256.f);

    float d0x = v0.x - mean, d0y = v0.y - mean, d0z = v0.z - mean, d0w = v0.w - mean;
    float d1x = v1.x - mean, d1y = v1.y - mean, d1z = v1.z - mean, d1w = v1.w - mean;
    float s2 = d0x * d0x + d0y * d0y + d0z * d0z + d0w * d0w
             + d1x * d1x + d1y * d1y + d1z * d1z + d1w * d1w;
#pragma unroll
    for (int o = 16; o; o >>= 1) s2 += __shfl_xor_sync(0xffffffffu, s2, o);
    float inv = rsqrtf(s2 * (1.f / 256.f) + 1e-5f);

    const float4* g4 = reinterpret_cast<const float4*>(g);
    const float4* b4 = reinterpret_cast<const float4*>(bb);
    float4 g0 = g4[lane * 2 + 0], g1 = g4[lane * 2 + 1];
    float4 bb0 = b4[lane * 2 + 0], bb1 = b4[lane * 2 + 1];

    float4 o0, o1;
    o0.x = d0x * inv * g0.x + bb0.x; o0.y = d0y * inv * g0.y + bb0.y;
    o0.z = d0z * inv * g0.z + bb0.z; o0.w = d0w * inv * g0.w + bb0.w;
    o1.x = d1x * inv * g1.x + bb1.x; o1.y = d1y * inv * g1.y + bb1.y;
    o1.z = d1z * inv * g1.z + bb1.z; o1.w = d1w * inv * g1.w + bb1.w;

    float4* out4 = reinterpret_cast<float4*>(out + (size_t)tok * DMODEL);
    out4[lane * 2 + 0] = o0;
    out4[lane * 2 + 1] = o1;

    if (outh) {
        __half2 h0 = __floats2half2_rn(o0.x, o0.y);
        __half2 h1 = __floats2half2_rn(o0.z, o0.w);
        __half2 h2 = __floats2half2_rn(o1.x, o1.y);
        __half2 h3 = __floats2half2_rn(o1.z, o1.w);
        uint4 hp;
        hp.x = *reinterpret_cast<uint32_t*>(&h0);
        hp.y = *reinterpret_cast<uint32_t*>(&h1);
        hp.z = *reinterpret_cast<uint32_t*>(&h2);
        hp.w = *reinterpret_cast<uint32_t*>(&h3);
        *reinterpret_cast<uint4*>(outh + (size_t)tok * DMODEL + lane * 8) = hp;
    }
}

// ---------------- launch ----------------
extern "C" void kernel_launch(void* const* d_in, const int* in_sizes, int n_in,
                              void* d_out, int out_size)
{
    const float* src    = (const float*)d_in[0];
    const float* pos    = (const float*)d_in[1];
    const float* refpts = (const float*)d_in[2];
    const int*   shapes = (const int*)  d_in[3];
    const int*   starts = (const int*)  d_in[4];
    const float* value_w = (const float*)d_in[5];
    const float* value_b = (const float*)d_in[6];
    const float* offs_w  = (const float*)d_in[7];
    const float* offs_b  = (const float*)d_in[8];
    const float* attn_w  = (const float*)d_in[9];
    const float* attn_b  = (const float*)d_in[10];
    const float* out_w   = (const float*)d_in[11];
    const float* out_b   = (const float*)d_in[12];
    const float* ln1_g   = (const float*)d_in[13];
    const float* ln1_b   = (const float*)d_in[14];
    const float* ff1_w   = (const float*)d_in[15];
    const float* ff1_b   = (const float*)d_in[16];
    const float* ff2_w   = (const float*)d_in[17];
    const float* ff2_b   = (const float*)d_in[18];
    const float* ln2_g   = (const float*)d_in[19];
    const float* ln2_b   = (const float*)d_in[20];
    float* outp = (float*)d_out;

    float *q, *offs, *aw, *src2, *x, *biasp;
    __half *qh, *value, *msdah, *xh, *ffh;
    __half *wtp, *wtu, *wtf1, *wtf2;
    cudaGetSymbolAddress((void**)&q,     g_q);
    cudaGetSymbolAddress((void**)&qh,    g_qh);
    cudaGetSymbolAddress((void**)&value, g_value);
    cudaGetSymbolAddress((void**)&offs,  g_offs);
    cudaGetSymbolAddress((void**)&aw,    g_aw);
    cudaGetSymbolAddress((void**)&msdah, g_msdah);
    cudaGetSymbolAddress((void**)&src2,  g_src2);
    cudaGetSymbolAddress((void**)&x,     g_x);
    cudaGetSymbolAddress((void**)&xh,    g_xh);
    cudaGetSymbolAddress((void**)&ffh,   g_ffh);
    cudaGetSymbolAddress((void**)&wtp,   g_wt_proj);
    cudaGetSymbolAddress((void**)&wtu,   g_wt_out);
    cudaGetSymbolAddress((void**)&wtf1,  g_wt_ff1);
    cudaGetSymbolAddress((void**)&wtf2,  g_wt_ff2);
    cudaGetSymbolAddress((void**)&biasp, g_bias_proj);

    cudaFuncSetAttribute(gemm_mma, cudaFuncAttributeMaxDynamicSharedMemorySize, GEMM_SMEM);

    const int M = MTOK;
    const int gy = (M + 127) / 128;

    // 0. fused weight prep + q = src + pos
    prep_add_kernel<<<(PA_TOTAL + 255) / 256, 256>>>(value_w, offs_w, attn_w, out_w, ff1_w, ff2_w,
                                                     value_b, offs_b, attn_b,
                                                     wtp, wtu, wtf1, wtf2, biasp,
                                                     src, pos, q, qh);

    // 1. fused projections: [value(fp16, transposed) | offs | aw] = q @ Wp^T
    gemm_mma<<<dim3(5, gy), 256, GEMM_SMEM>>>(qh, 256, wtp, 256, biasp,
                                              nullptr, value, offs, aw, M, 256, 640, 0, 2);

    // 2. deformable sampling with fused softmax (transposed value)
    msda_kernel<<<M, 256>>>(value, offs, aw, refpts, shapes, starts, msdah);

    // 3. output projection: src2 = msda @ out_w + out_b
    gemm_mma<<<dim3(2, gy), 256, GEMM_SMEM>>>(msdah, 256, wtu, 256, out_b,
                                              src2, nullptr, nullptr, nullptr, M, 256, 256, 0, 0);

    // 4. x = LN(q + src2)  (+ fp16 copy)
    add_ln_kernel<<<(M * 32 + 255) / 256, 256>>>(q, src2, ln1_g, ln1_b, x, xh);

    // 5. ffh = relu(x @ ff1_w + ff1_b) -> fp16
    gemm_mma<<<dim3(8, gy), 256, GEMM_SMEM>>>(xh, 256, wtf1, 256, ff1_b,
                                              nullptr, ffh, nullptr, nullptr, M, 256, 1024, 1, 1);

    // 6. f = ffh @ ff2_w + ff2_b  (into 'offs' buffer)
    gemm_mma<<<dim3(2, gy), 256, GEMM_SMEM>>>(ffh, 1024, wtf2, 1024, ff2_b,
                                              offs, nullptr, nullptr, nullptr, M, 1024, 256, 0, 0);

    // 7. out = LN(x + f)
    add_ln_kernel<<<(M * 32 + 255) / 256, 256>>>(x, offs, ln2_g, ln2_b, outp, nullptr);
}

// round 10
// speedup vs baseline: 1.0310x; 1.0310x over previous
#include <cuda_runtime.h>
#include <cuda_fp16.h>
#include <cstdint>
#include <math.h>

// ---------------- problem constants ----------------
#define Bq    4
#define LIN   13294
#define MTOK  (Bq * LIN)      // 53176
#define DMODEL 256
#define NHEAD 8
#define NLVL  4
#define NPTS  4
#define DH    32
#define DFF   1024

// ---------------- scratch (device globals) ----------------
__device__ float  g_q    [(size_t)MTOK * DMODEL];
__device__ __half g_qh   [(size_t)MTOK * DMODEL];
__device__ __half g_value[(size_t)MTOK * DMODEL];   // TRANSPOSED: [head][tok][32]
__device__ float  g_offs [(size_t)MTOK * DMODEL];   // reused for ff2 out
__device__ float  g_aw   [(size_t)MTOK * 128];      // raw logits
__device__ __half g_msdah[(size_t)MTOK * DMODEL];
__device__ float  g_src2 [(size_t)MTOK * DMODEL];
__device__ float  g_x    [(size_t)MTOK * DMODEL];
__device__ __half g_xh   [(size_t)MTOK * DMODEL];
__device__ __half g_ffh  [(size_t)MTOK * DFF];
// weights: Wt[N, K] fp16 K-major
__device__ __half g_wt_proj[640 * 256];
__device__ __half g_wt_out [256 * 256];
__device__ __half g_wt_ff1 [1024 * 256];
__device__ __half g_wt_ff2 [256 * 1024];
__device__ float  g_bias_proj[640];

// ---------------- helpers ----------------
__device__ __forceinline__ uint32_t smem_u32(const void* p) {
    uint32_t a;
    asm("{ .reg .u64 t; cvta.to.shared.u64 t, %1; cvt.u32.u64 %0, t; }" : "=r"(a) : "l"(p));
    return a;
}
#define CP_ASYNC16(dst, src) \
    asm volatile("cp.async.cg.shared.global [%0], [%1], 16;\n" :: "r"(dst), "l"(src) : "memory")
#define CP_COMMIT() asm volatile("cp.async.commit_group;\n" ::: "memory")
#define CP_WAIT(n)  asm volatile("cp.async.wait_group %0;\n" :: "n"(n) : "memory")

__device__ __forceinline__ void ldmatrix_x4(uint32_t& r0, uint32_t& r1, uint32_t& r2, uint32_t& r3, uint32_t addr) {
    asm volatile("ldmatrix.sync.aligned.m8n8.x4.shared.b16 {%0,%1,%2,%3}, [%4];"
                 : "=r"(r0), "=r"(r1), "=r"(r2), "=r"(r3) : "r"(addr));
}
__device__ __forceinline__ void mma_f16(float* c, const uint32_t* a, const uint32_t* b) {
    asm volatile("mma.sync.aligned.m16n8k16.row.col.f32.f16.f16.f32 "
                 "{%0,%1,%2,%3}, {%4,%5,%6,%7}, {%8,%9}, {%0,%1,%2,%3};"
                 : "+f"(c[0]), "+f"(c[1]), "+f"(c[2]), "+f"(c[3])
                 : "r"(a[0]), "r"(a[1]), "r"(a[2]), "r"(a[3]), "r"(b[0]), "r"(b[1]));
}

// ---------------- fp16 warp-MMA GEMM, 4-stage cp.async pipeline ------------
// mode 0: Cf fp32 [M,N]. mode 1: Ch fp16 [M,N].
// mode 2: cols 0-255 -> Ch TRANSPOSED value layout [head][tok][32];
//         cols 256-511 -> C2 (fp32, stride 256); 512-639 -> C3 (fp32, 128).
#define PADS 40
#define STAGE_ELEMS (128 * PADS)
#define NSTAGE 4
#define GEMM_SMEM (2 * NSTAGE * STAGE_ELEMS * 2)   // 81920 bytes

__global__ __launch_bounds__(256, 2)
void gemm_mma(const __half* __restrict__ A, int lda,
              const __half* __restrict__ B, int ldb,
              const float* __restrict__ bias,
              float* __restrict__ Cf, __half* __restrict__ Ch,
              float* __restrict__ C2, float* __restrict__ C3,
              int M, int K, int N, int relu, int mode)
{
    extern __shared__ __align__(16) __half dynsmem[];

    const int tid  = threadIdx.x;
    const int wid  = tid >> 5;
    const int lane = tid & 31;
    const int wm   = wid & 3;
    const int wn   = wid >> 2;
    const int row0 = blockIdx.y * 128;
    const int col0 = blockIdx.x * 128;

    const uint32_t sbase = smem_u32(dynsmem);
    const int NC = K >> 5;

    float acc[2][8][4];
#pragma unroll
    for (int i = 0; i < 2; i++)
#pragma unroll
        for (int j = 0; j < 8; j++)
#pragma unroll
            for (int t = 0; t < 4; t++) acc[i][j][t] = 0.f;

#define LOAD_STAGE(buf, cc) do {                                              \
        int _kc = (cc) << 5;                                                  \
        uint32_t _dA = sbase + (buf) * (STAGE_ELEMS * 2);                     \
        uint32_t _dB = sbase + (NSTAGE + (buf)) * (STAGE_ELEMS * 2);          \
        _Pragma("unroll")                                                     \
        for (int _i = 0; _i < 2; ++_i) {                                      \
            int _c = tid + _i * 256;                                          \
            int _r = _c >> 2, _k8 = _c & 3;                                   \
            int _gr = row0 + _r; if (_gr >= M) _gr = M - 1;                   \
            CP_ASYNC16(_dA + (_r * PADS + _k8 * 8) * 2,                       \
                       A + (size_t)_gr * lda + _kc + _k8 * 8);                \
        }                                                                     \
        _Pragma("unroll")                                                     \
        for (int _i = 0; _i < 2; ++_i) {                                      \
            int _c = tid + _i * 256;                                          \
            int _r = _c >> 2, _k8 = _c & 3;                                   \
            CP_ASYNC16(_dB + (_r * PADS + _k8 * 8) * 2,                       \
                       B + (size_t)(col0 + _r) * ldb + _kc + _k8 * 8);        \
        }                                                                     \
    } while (0)

    LOAD_STAGE(0, 0); CP_COMMIT();
    LOAD_STAGE(1, 1); CP_COMMIT();
    LOAD_STAGE(2, 2); CP_COMMIT();

    for (int c = 0; c < NC; ++c) {
        const int buf = c & 3;
        CP_WAIT(2);
        __syncthreads();

        if (c + 3 < NC) LOAD_STAGE((c + 3) & 3, c + 3);
        CP_COMMIT();

        const uint32_t baseA = sbase + buf * (STAGE_ELEMS * 2);
        const uint32_t baseB = sbase + (NSTAGE + buf) * (STAGE_ELEMS * 2);

#pragma unroll
        for (int kk = 0; kk < 32; kk += 16) {
            uint32_t a[2][4];
#pragma unroll
            for (int mt = 0; mt < 2; mt++) {
                int r = wm * 32 + mt * 16 + (lane & 15);
                int kc = kk + ((lane & 16) ? 8 : 0);
                ldmatrix_x4(a[mt][0], a[mt][1], a[mt][2], a[mt][3],
                            baseA + (r * PADS + kc) * 2);
            }
            uint32_t b[8][2];
#pragma unroll
            for (int np = 0; np < 4; np++) {
                int n = wn * 64 + np * 16 + (lane & 7) + ((lane & 16) ? 8 : 0);
                int kc = kk + ((lane & 8) ? 8 : 0);
                ldmatrix_x4(b[2 * np][0], b[2 * np][1], b[2 * np + 1][0], b[2 * np + 1][1],
                            baseB + (n * PADS + kc) * 2);
            }
#pragma unroll
            for (int mt = 0; mt < 2; mt++)
#pragma unroll
                for (int nt = 0; nt < 8; nt++)
                    mma_f16(acc[mt][nt], a[mt], b[nt]);
        }
        __syncthreads();
    }

    // ---- epilogue ----
    float* outf = Cf;
    __half* outh = Ch;
    int ostride = N, coff = 0;
    int write_kind = (mode == 1) ? 1 : 0;
    if (mode == 2) {
        if (col0 < 256)      { outh = Ch; write_kind = 2; }
        else if (col0 < 512) { outf = C2; ostride = 256; coff = 256; }
        else                 { outf = C3; ostride = 128; coff = 512; }
    }

#pragma unroll
    for (int mt = 0; mt < 2; mt++) {
#pragma unroll
        for (int half_i = 0; half_i < 2; half_i++) {
            int r = row0 + wm * 32 + mt * 16 + (lane >> 2) + half_i * 8;
            if (r >= M) continue;
#pragma unroll
            for (int nt = 0; nt < 8; nt++) {
                int cidx = col0 + wn * 64 + nt * 8 + (lane & 3) * 2;
                float v0 = acc[mt][nt][half_i * 2 + 0] + bias[cidx];
                float v1 = acc[mt][nt][half_i * 2 + 1] + bias[cidx + 1];
                if (relu) { v0 = fmaxf(v0, 0.f); v1 = fmaxf(v1, 0.f); }
                if (write_kind == 2) {
                    __half2 hv;
                    hv.x = __float2half_rn(v0);
                    hv.y = __float2half_rn(v1);
                    size_t addr = ((size_t)(cidx >> 5) * MTOK + r) * 32 + (cidx & 31);
                    *reinterpret_cast<__half2*>(outh + addr) = hv;
                } else if (write_kind == 1) {
                    __half2 hv;
                    hv.x = __float2half_rn(v0);
                    hv.y = __float2half_rn(v1);
                    *reinterpret_cast<__half2*>(outh + (size_t)r * ostride + cidx) = hv;
                } else {
                    float2 o = make_float2(v0, v1);
                    *reinterpret_cast<float2*>(outf + (size_t)r * ostride + (cidx - coff)) = o;
                }
            }
        }
    }
#undef LOAD_STAGE
}

// ---------------- fused weight prep + q = src + pos ------------------------
__device__ __forceinline__ void wtr1(const float* __restrict__ W, __half* __restrict__ Wt,
                                     int K_, int N_, int i)
{
    int k = i / N_, n = i % N_;
    Wt[(size_t)n * K_ + k] = __float2half_rn(W[i]);
}

#define PREP_ITEMS 754304
#define ADD_ITEMS  (MTOK * DMODEL / 4)
#define PA_TOTAL   (PREP_ITEMS + ADD_ITEMS)

__global__ void prep_add_kernel(const float* __restrict__ vW, const float* __restrict__ oW,
                                const float* __restrict__ aW, const float* __restrict__ uW,
                                const float* __restrict__ f1W, const float* __restrict__ f2W,
                                const float* __restrict__ vb, const float* __restrict__ ob,
                                const float* __restrict__ ab,
                                __half* __restrict__ wtp, __half* __restrict__ wtu,
                                __half* __restrict__ wtf1, __half* __restrict__ wtf2,
                                float* __restrict__ biasp,
                                const float* __restrict__ srca, const float* __restrict__ posb,
                                float* __restrict__ q, __half* __restrict__ qh)
{
    int i = blockIdx.x * blockDim.x + threadIdx.x;
    if (i >= PREP_ITEMS) {
        int t = i - PREP_ITEMS;
        if (t >= ADD_ITEMS) return;
        float4 x = reinterpret_cast<const float4*>(srca)[t];
        float4 y = reinterpret_cast<const float4*>(posb)[t];
        x.x += y.x; x.y += y.y; x.z += y.z; x.w += y.w;
        reinterpret_cast<float4*>(q)[t] = x;
        __half2 h0 = __floats2half2_rn(x.x, x.y);
        __half2 h1 = __floats2half2_rn(x.z, x.w);
        uint2 hp;
        hp.x = *reinterpret_cast<uint32_t*>(&h0);
        hp.y = *reinterpret_cast<uint32_t*>(&h1);
        reinterpret_cast<uint2*>(qh)[t] = hp;
        return;
    }
    if (i < 65536)       { wtr1(vW, wtp, 256, 256, i); return; }
    i -= 65536;
    if (i < 65536)       { wtr1(oW, wtp + 256 * 256, 256, 256, i); return; }
    i -= 65536;
    if (i < 32768)       { wtr1(aW, wtp + 512 * 256, 256, 128, i); return; }
    i -= 32768;
    if (i < 65536)       { wtr1(uW, wtu, 256, 256, i); return; }
    i -= 65536;
    if (i < 262144)      { wtr1(f1W, wtf1, 256, 1024, i); return; }
    i -= 262144;
    if (i < 262144)      { wtr1(f2W, wtf2, 1024, 256, i); return; }
    i -= 262144;
    if (i < 256)         { biasp[i] = vb[i]; return; }
    if (i < 512)         { biasp[i] = ob[i - 256]; return; }
    if (i < 640)         { biasp[i] = ab[i - 512]; return; }
}

// ---------------- MSDA v4: paired-corner coalesced gathers -----------------
// value layout: [head][MTOK][32 ch] (64B per token-head). The two x-corners of
// a point are 64B-adjacent -> 8 lanes (2 corner-sel x 4 chan-quads) load both
// corners of a y-row in ONE 128B-coalesced uint4 access.
// Precompute: lane j=lane&15 computes point j; hi half (lane>=16) keeps the
// x1-corner variant so srcLane = pt + 16*sel delivers per-corner state.
__global__ __launch_bounds__(256)
void msda_kernel(const __half* __restrict__ value, const float* __restrict__ offs,
                 const float* __restrict__ aw, const float* __restrict__ ref,
                 const int* __restrict__ shapes, const int* __restrict__ starts,
                 __half* __restrict__ outh)
{
    const int tok = blockIdx.x;
    const int h = threadIdx.x >> 5;
    const int lane = threadIdx.x & 31;
    const int j = lane & 15;
    const int hi = lane >> 4;
    const int b = tok / LIN;
    const int l = j >> 2;

    // ---- per-point precompute ----
    const int Hl = shapes[l * 2 + 0];
    const int Wl = shapes[l * 2 + 1];
    const int st = starts[l];
    const float fW = (float)Wl, fH = (float)Hl;
    const float rx = ref[(size_t)tok * 8 + l * 2 + 0];
    const float ry = ref[(size_t)tok * 8 + l * 2 + 1];
    const float2 off = *reinterpret_cast<const float2*>(offs + (size_t)tok * 256 + h * 32 + 2 * j);

    float logit = aw[(size_t)tok * 128 + h * 16 + j];
    float m = logit;
#pragma unroll
    for (int o = 8; o; o >>= 1) m = fmaxf(m, __shfl_xor_sync(0xffffffffu, m, o, 16));
    float e = expf(logit - m);
    float s = e;
#pragma unroll
    for (int o = 8; o; o >>= 1) s += __shfl_xor_sync(0xffffffffu, s, o, 16);
    float wgt = e / s;

    float x = (rx + off.x / fW) * fW - 0.5f;
    float y = (ry + off.y / fH) * fH - 0.5f;
    float x0f = floorf(x), y0f = floorf(y);
    float dx = x - x0f, dy = y - y0f;
    int x0 = (int)x0f, y0 = (int)y0f;
    int x1 = x0 + 1, y1 = y0 + 1;

    bool xv0 = (x0 >= 0) & (x0 < Wl);
    bool xv1 = (x1 >= 0) & (x1 < Wl);
    bool yv0 = (y0 >= 0) & (y0 < Hl);
    bool yv1 = (y1 >= 0) & (y1 < Hl);

    float w00 = (xv0 && yv0) ? wgt * (1.f - dx) * (1.f - dy) : 0.f;
    float w10 = (xv1 && yv0) ? wgt * dx * (1.f - dy) : 0.f;
    float w01 = (xv0 && yv1) ? wgt * (1.f - dx) * dy : 0.f;
    float w11 = (xv1 && yv1) ? wgt * dx * dy : 0.f;

    int cx0 = min(max(x0, 0), Wl - 1), cx1 = min(max(x1, 0), Wl - 1);
    int cy0 = min(max(y0, 0), Hl - 1), cy1 = min(max(y1, 0), Hl - 1);
    const int base = b * LIN + st;
    // hi half holds the x1-corner variant
    int ixy0 = base + cy0 * Wl + (hi ? cx1 : cx0);   // (y0, x_hi)
    int ixy1 = base + cy1 * Wl + (hi ? cx1 : cx0);   // (y1, x_hi)
    float uwy0 = hi ? w10 : w00;
    float uwy1 = hi ? w11 : w01;

    // ---- gather: 4 passes x 4 points; 8 lanes cover one point (2 corners) --
    const int pg  = lane >> 3;        // point within pass (0..3)
    const int sel = (lane >> 2) & 1;  // x-corner select
    const int c4  = lane & 3;         // channel quad
    const __half* vch = value + (size_t)h * MTOK * 32 + c4 * 8;
    float acc[8] = {0.f, 0.f, 0.f, 0.f, 0.f, 0.f, 0.f, 0.f};

#pragma unroll
    for (int p = 0; p < 4; p++) {
        const int pt = p * 4 + pg;
        const int srcl = pt + (sel << 4);
        int ay = __shfl_sync(0xffffffffu, ixy0, srcl);
        int by = __shfl_sync(0xffffffffu, ixy1, srcl);
        float uy = __shfl_sync(0xffffffffu, uwy0, srcl);
        float vy = __shfl_sync(0xffffffffu, uwy1, srcl);

        uint4 r0 = *reinterpret_cast<const uint4*>(vch + (size_t)ay * 32);
        uint4 r1 = *reinterpret_cast<const uint4*>(vch + (size_t)by * 32);

#define ACC8(rv, u) do {                                                      \
        const __half2* _h = reinterpret_cast<const __half2*>(&(rv));          \
        _Pragma("unroll")                                                     \
        for (int _k = 0; _k < 4; _k++) {                                      \
            float2 _f = __half22float2(_h[_k]);                               \
            acc[2 * _k + 0] = fmaf(u, _f.x, acc[2 * _k + 0]);                 \
            acc[2 * _k + 1] = fmaf(u, _f.y, acc[2 * _k + 1]);                 \
        } } while (0)

        ACC8(r0, uy);
        ACC8(r1, vy);
#undef ACC8
    }

    // ---- reduce over x-corner (xor 4) and point groups (xor 8, 16) ----
#pragma unroll
    for (int o = 4; o <= 16; o <<= 1) {
#pragma unroll
        for (int k = 0; k < 8; k++)
            acc[k] += __shfl_xor_sync(0xffffffffu, acc[k], o);
    }

    if (lane < 4) {
        __half2 h0 = __floats2half2_rn(acc[0], acc[1]);
        __half2 h1 = __floats2half2_rn(acc[2], acc[3]);
        __half2 h2 = __floats2half2_rn(acc[4], acc[5]);
        __half2 h3 = __floats2half2_rn(acc[6], acc[7]);
        uint4 o;
        o.x = *reinterpret_cast<uint32_t*>(&h0);
        o.y = *reinterpret_cast<uint32_t*>(&h1);
        o.z = *reinterpret_cast<uint32_t*>(&h2);
        o.w = *reinterpret_cast<uint32_t*>(&h3);
        *reinterpret_cast<uint4*>(outh + (size_t)tok * DMODEL + h * DH + lane * 8) = o;
    }
}

// ---------------- warp-per-token residual add + LayerNorm ------------------
__global__ __launch_bounds__(256)
void add_ln_kernel(const float* __restrict__ a, const float* __restrict__ r,
                   const float* __restrict__ g, const float* __restrict__ bb,
                   float* __restrict__ out, __half* __restrict__ outh)
{
    const int tok = (blockIdx.x * blockDim.x + threadIdx.x) >> 5;
    const int lane = threadIdx.x & 31;
    if (tok >= MTOK) return;

    const float4* a4 = reinterpret_cast<const float4*>(a + (size_t)tok * DMODEL);
    const float4* r4 = reinterpret_cast<const float4*>(r + (size_t)tok * DMODEL);
    float4 v0 = a4[lane * 2 + 0], v1 = a4[lane * 2 + 1];
    float4 u0 = r4[lane * 2 + 0], u1 = r4[lane * 2 + 1];
    v0.x += u0.x; v0.y += u0.y; v0.z += u0.z; v0.w += u0.w;
    v1.x += u1.x; v1.y += u1.y; v1.z += u1.z; v1.w += u1.w;

    float s = v0.x + v0.y + v0.z + v0.w + v1.x + v1.y + v1.z + v1.w;
#pragma unroll
    for (int o = 16; o; o >>= 1) s += __shfl_xor_sync(0xffffffffu, s, o);
    float mean = s * (1.f / 256.f);

    float d0x = v0.x - mean, d0y = v0.y - mean, d0z = v0.z - mean, d0w = v0.w - mean;
    float d1x = v1.x - mean, d1y = v1.y - mean, d1z = v1.z - mean, d1w = v1.w - mean;
    float s2 = d0x * d0x + d0y * d0y + d0z * d0z + d0w * d0w
             + d1x * d1x + d1y * d1y + d1z * d1z + d1w * d1w;
#pragma unroll
    for (int o = 16; o; o >>= 1) s2 += __shfl_xor_sync(0xffffffffu, s2, o);
    float inv = rsqrtf(s2 * (1.f / 256.f) + 1e-5f);

    const float4* g4 = reinterpret_cast<const float4*>(g);
    const float4* b4 = reinterpret_cast<const float4*>(bb);
    float4 g0 = g4[lane * 2 + 0], g1 = g4[lane * 2 + 1];
    float4 bb0 = b4[lane * 2 + 0], bb1 = b4[lane * 2 + 1];

    float4 o0, o1;
    o0.x = d0x * inv * g0.x + bb0.x; o0.y = d0y * inv * g0.y + bb0.y;
    o0.z = d0z * inv * g0.z + bb0.z; o0.w = d0w * inv * g0.w + bb0.w;
    o1.x = d1x * inv * g1.x + bb1.x; o1.y = d1y * inv * g1.y + bb1.y;
    o1.z = d1z * inv * g1.z + bb1.z; o1.w = d1w * inv * g1.w + bb1.w;

    float4* out4 = reinterpret_cast<float4*>(out + (size_t)tok * DMODEL);
    out4[lane * 2 + 0] = o0;
    out4[lane * 2 + 1] = o1;

    if (outh) {
        __half2 h0 = __floats2half2_rn(o0.x, o0.y);
        __half2 h1 = __floats2half2_rn(o0.z, o0.w);
        __half2 h2 = __floats2half2_rn(o1.x, o1.y);
        __half2 h3 = __floats2half2_rn(o1.z, o1.w);
        uint4 hp;
        hp.x = *reinterpret_cast<uint32_t*>(&h0);
        hp.y = *reinterpret_cast<uint32_t*>(&h1);
        hp.z = *reinterpret_cast<uint32_t*>(&h2);
        hp.w = *reinterpret_cast<uint32_t*>(&h3);
        *reinterpret_cast<uint4*>(outh + (size_t)tok * DMODEL + lane * 8) = hp;
    }
}

// ---------------- launch ----------------
extern "C" void kernel_launch(void* const* d_in, const int* in_sizes, int n_in,
                              void* d_out, int out_size)
{
    const float* src    = (const float*)d_in[0];
    const float* pos    = (const float*)d_in[1];
    const float* refpts = (const float*)d_in[2];
    const int*   shapes = (const int*)  d_in[3];
    const int*   starts = (const int*)  d_in[4];
    const float* value_w = (const float*)d_in[5];
    const float* value_b = (const float*)d_in[6];
    const float* offs_w  = (const float*)d_in[7];
    const float* offs_b  = (const float*)d_in[8];
    const float* attn_w  = (const float*)d_in[9];
    const float* attn_b  = (const float*)d_in[10];
    const float* out_w   = (const float*)d_in[11];
    const float* out_b   = (const float*)d_in[12];
    const float* ln1_g   = (const float*)d_in[13];
    const float* ln1_b   = (const float*)d_in[14];
    const float* ff1_w   = (const float*)d_in[15];
    const float* ff1_b   = (const float*)d_in[16];
    const float* ff2_w   = (const float*)d_in[17];
    const float* ff2_b   = (const float*)d_in[18];
    const float* ln2_g   = (const float*)d_in[19];
    const float* ln2_b   = (const float*)d_in[20];
    float* outp = (float*)d_out;

    float *q, *offs, *aw, *src2, *x, *biasp;
    __half *qh, *value, *msdah, *xh, *ffh;
    __half *wtp, *wtu, *wtf1, *wtf2;
    cudaGetSymbolAddress((void**)&q,     g_q);
    cudaGetSymbolAddress((void**)&qh,    g_qh);
    cudaGetSymbolAddress((void**)&value, g_value);
    cudaGetSymbolAddress((void**)&offs,  g_offs);
    cudaGetSymbolAddress((void**)&aw,    g_aw);
    cudaGetSymbolAddress((void**)&msdah, g_msdah);
    cudaGetSymbolAddress((void**)&src2,  g_src2);
    cudaGetSymbolAddress((void**)&x,     g_x);
    cudaGetSymbolAddress((void**)&xh,    g_xh);
    cudaGetSymbolAddress((void**)&ffh,   g_ffh);
    cudaGetSymbolAddress((void**)&wtp,   g_wt_proj);
    cudaGetSymbolAddress((void**)&wtu,   g_wt_out);
    cudaGetSymbolAddress((void**)&wtf1,  g_wt_ff1);
    cudaGetSymbolAddress((void**)&wtf2,  g_wt_ff2);
    cudaGetSymbolAddress((void**)&biasp, g_bias_proj);

    cudaFuncSetAttribute(gemm_mma, cudaFuncAttributeMaxDynamicSharedMemorySize, GEMM_SMEM);

    const int M = MTOK;
    const int gy = (M + 127) / 128;

    // 0. fused weight prep + q = src + pos
    prep_add_kernel<<<(PA_TOTAL + 255) / 256, 256>>>(value_w, offs_w, attn_w, out_w, ff1_w, ff2_w,
                                                     value_b, offs_b, attn_b,
                                                     wtp, wtu, wtf1, wtf2, biasp,
                                                     src, pos, q, qh);

    // 1. fused projections: [value(fp16, transposed) | offs | aw] = q @ Wp^T
    gemm_mma<<<dim3(5, gy), 256, GEMM_SMEM>>>(qh, 256, wtp, 256, biasp,
                                              nullptr, value, offs, aw, M, 256, 640, 0, 2);

    // 2. deformable sampling with fused softmax (paired-corner gathers)
    msda_kernel<<<M, 256>>>(value, offs, aw, refpts, shapes, starts, msdah);

    // 3. output projection: src2 = msda @ out_w + out_b
    gemm_mma<<<dim3(2, gy), 256, GEMM_SMEM>>>(msdah, 256, wtu, 256, out_b,
                                              src2, nullptr, nullptr, nullptr, M, 256, 256, 0, 0);

    // 4. x = LN(q + src2)  (+ fp16 copy)
    add_ln_kernel<<<(M * 32 + 255) / 256, 256>>>(q, src2, ln1_g, ln1_b, x, xh);

    // 5. ffh = relu(x @ ff1_w + ff1_b) -> fp16
    gemm_mma<<<dim3(8, gy), 256, GEMM_SMEM>>>(xh, 256, wtf1, 256, ff1_b,
                                              nullptr, ffh, nullptr, nullptr, M, 256, 1024, 1, 1);

    // 6. f = ffh @ ff2_w + ff2_b  (into 'offs' buffer)
    gemm_mma<<<dim3(2, gy), 256, GEMM_SMEM>>>(ffh, 1024, wtf2, 1024, ff2_b,
                                              offs, nullptr, nullptr, nullptr, M, 1024, 256, 0, 0);

    // 7. out = LN(x + f)
    add_ln_kernel<<<(M * 32 + 255) / 256, 256>>>(x, offs, ln2_g, ln2_b, outp, nullptr);
}

// round 11
// speedup vs baseline: 1.0615x; 1.0296x over previous
#include <cuda_runtime.h>
#include <cuda_fp16.h>
#include <cstdint>
#include <math.h>

// ---------------- problem constants ----------------
#define Bq    4
#define LIN   13294
#define MTOK  (Bq * LIN)      // 53176
#define DMODEL 256
#define NHEAD 8
#define NLVL  4
#define NPTS  4
#define DH    32
#define DFF   1024

// ---------------- scratch (device globals) ----------------
__device__ float  g_q    [(size_t)MTOK * DMODEL];
__device__ __half g_qh   [(size_t)MTOK * DMODEL];
__device__ __half g_value[(size_t)MTOK * DMODEL];   // row-major [tok][256]
__device__ float  g_offs [(size_t)MTOK * DMODEL];   // reused for ff2 out
__device__ float  g_aw   [(size_t)MTOK * 128];      // raw logits
__device__ __half g_msdah[(size_t)MTOK * DMODEL];
__device__ float  g_src2 [(size_t)MTOK * DMODEL];
__device__ float  g_x    [(size_t)MTOK * DMODEL];
__device__ __half g_xh   [(size_t)MTOK * DMODEL];
__device__ __half g_ffh  [(size_t)MTOK * DFF];
// weights: Wt[N, K] fp16 K-major
__device__ __half g_wt_proj[640 * 256];
__device__ __half g_wt_out [256 * 256];
__device__ __half g_wt_ff1 [1024 * 256];
__device__ __half g_wt_ff2 [256 * 1024];
__device__ float  g_bias_proj[640];

// ---------------- helpers ----------------
__device__ __forceinline__ uint32_t smem_u32(const void* p) {
    uint32_t a;
    asm("{ .reg .u64 t; cvta.to.shared.u64 t, %1; cvt.u32.u64 %0, t; }" : "=r"(a) : "l"(p));
    return a;
}
#define CP_ASYNC16(dst, src) \
    asm volatile("cp.async.cg.shared.global [%0], [%1], 16;\n" :: "r"(dst), "l"(src) : "memory")
#define CP_COMMIT() asm volatile("cp.async.commit_group;\n" ::: "memory")
#define CP_WAIT(n)  asm volatile("cp.async.wait_group %0;\n" :: "n"(n) : "memory")

__device__ __forceinline__ void ldmatrix_x4(uint32_t& r0, uint32_t& r1, uint32_t& r2, uint32_t& r3, uint32_t addr) {
    asm volatile("ldmatrix.sync.aligned.m8n8.x4.shared.b16 {%0,%1,%2,%3}, [%4];"
                 : "=r"(r0), "=r"(r1), "=r"(r2), "=r"(r3) : "r"(addr));
}
__device__ __forceinline__ void mma_f16(float* c, const uint32_t* a, const uint32_t* b) {
    asm volatile("mma.sync.aligned.m16n8k16.row.col.f32.f16.f16.f32 "
                 "{%0,%1,%2,%3}, {%4,%5,%6,%7}, {%8,%9}, {%0,%1,%2,%3};"
                 : "+f"(c[0]), "+f"(c[1]), "+f"(c[2]), "+f"(c[3])
                 : "r"(a[0]), "r"(a[1]), "r"(a[2]), "r"(a[3]), "r"(b[0]), "r"(b[1]));
}

// ---------------- fp16 warp-MMA GEMM, pair-granularity double buffer -------
// 4 smem buffers grouped as 2 pairs; each mainloop iteration consumes 64 K
// (2 chunks) behind ONE cp.async.wait_group + ONE __syncthreads.
// mode 0: Cf fp32 [M,N]. mode 1: Ch fp16 [M,N].
// mode 2: cols 0-255 -> Ch fp16 (value, stride 256); 256-511 -> C2 (fp32,256);
//         512-639 -> C3 (fp32, 128). bias indexed by global col.
#define PADS 40
#define STAGE_ELEMS (128 * PADS)
#define NSTAGE 4
#define GEMM_SMEM (2 * NSTAGE * STAGE_ELEMS * 2)   // 81920 bytes

__global__ __launch_bounds__(256, 2)
void gemm_mma(const __half* __restrict__ A, int lda,
              const __half* __restrict__ B, int ldb,
              const float* __restrict__ bias,
              float* __restrict__ Cf, __half* __restrict__ Ch,
              float* __restrict__ C2, float* __restrict__ C3,
              int M, int K, int N, int relu, int mode)
{
    extern __shared__ __align__(16) __half dynsmem[];

    const int tid  = threadIdx.x;
    const int wid  = tid >> 5;
    const int lane = tid & 31;
    const int wm   = wid & 3;
    const int wn   = wid >> 2;
    const int row0 = blockIdx.y * 128;
    const int col0 = blockIdx.x * 128;

    const uint32_t sbase = smem_u32(dynsmem);
    const int NC2 = K >> 6;   // 64-K pairs; K must be a multiple of 64

    float acc[2][8][4];
#pragma unroll
    for (int i = 0; i < 2; i++)
#pragma unroll
        for (int j = 0; j < 8; j++)
#pragma unroll
            for (int t = 0; t < 4; t++) acc[i][j][t] = 0.f;

#define LOAD_STAGE(buf, cc) do {                                              \
        int _kc = (cc) << 5;                                                  \
        uint32_t _dA = sbase + (buf) * (STAGE_ELEMS * 2);                     \
        uint32_t _dB = sbase + (NSTAGE + (buf)) * (STAGE_ELEMS * 2);          \
        _Pragma("unroll")                                                     \
        for (int _i = 0; _i < 2; ++_i) {                                      \
            int _c = tid + _i * 256;                                          \
            int _r = _c >> 2, _k8 = _c & 3;                                   \
            int _gr = row0 + _r; if (_gr >= M) _gr = M - 1;                   \
            CP_ASYNC16(_dA + (_r * PADS + _k8 * 8) * 2,                       \
                       A + (size_t)_gr * lda + _kc + _k8 * 8);                \
        }                                                                     \
        _Pragma("unroll")                                                     \
        for (int _i = 0; _i < 2; ++_i) {                                      \
            int _c = tid + _i * 256;                                          \
            int _r = _c >> 2, _k8 = _c & 3;                                   \
            CP_ASYNC16(_dB + (_r * PADS + _k8 * 8) * 2,                       \
                       B + (size_t)(col0 + _r) * ldb + _kc + _k8 * 8);        \
        }                                                                     \
    } while (0)

    // preload pair 0 (buffers 0,1) as one commit group
    LOAD_STAGE(0, 0);
    LOAD_STAGE(1, 1);
    CP_COMMIT();

    for (int c = 0; c < NC2; ++c) {
        CP_WAIT(0);            // pair c landed (only outstanding group)
        __syncthreads();       // all warps done with the pair being overwritten

        if (c + 1 < NC2) {     // prefetch pair c+1 into the other 2 buffers
            const int pb = ((c + 1) & 1) << 1;
            LOAD_STAGE(pb, 2 * (c + 1));
            LOAD_STAGE(pb + 1, 2 * (c + 1) + 1);
        }
        CP_COMMIT();

        const int cb = (c & 1) << 1;
#pragma unroll
        for (int half2_i = 0; half2_i < 2; half2_i++) {
            const uint32_t baseA = sbase + (cb + half2_i) * (STAGE_ELEMS * 2);
            const uint32_t baseB = sbase + (NSTAGE + cb + half2_i) * (STAGE_ELEMS * 2);

#pragma unroll
            for (int kk = 0; kk < 32; kk += 16) {
                uint32_t a[2][4];
#pragma unroll
                for (int mt = 0; mt < 2; mt++) {
                    int r = wm * 32 + mt * 16 + (lane & 15);
                    int kc = kk + ((lane & 16) ? 8 : 0);
                    ldmatrix_x4(a[mt][0], a[mt][1], a[mt][2], a[mt][3],
                                baseA + (r * PADS + kc) * 2);
                }
                uint32_t b[8][2];
#pragma unroll
                for (int np = 0; np < 4; np++) {
                    int n = wn * 64 + np * 16 + (lane & 7) + ((lane & 16) ? 8 : 0);
                    int kc = kk + ((lane & 8) ? 8 : 0);
                    ldmatrix_x4(b[2 * np][0], b[2 * np][1], b[2 * np + 1][0], b[2 * np + 1][1],
                                baseB + (n * PADS + kc) * 2);
                }
#pragma unroll
                for (int mt = 0; mt < 2; mt++)
#pragma unroll
                    for (int nt = 0; nt < 8; nt++)
                        mma_f16(acc[mt][nt], a[mt], b[nt]);
            }
        }
    }

    // ---- epilogue ----
    float* outf = Cf;
    __half* outh = Ch;
    int ostride = N, coff = 0;
    int write_half = (mode == 1);
    if (mode == 2) {
        if (col0 < 256)      { outh = Ch; ostride = 256; coff = 0; write_half = 1; }
        else if (col0 < 512) { outf = C2; ostride = 256; coff = 256; }
        else                 { outf = C3; ostride = 128; coff = 512; }
    }

#pragma unroll
    for (int mt = 0; mt < 2; mt++) {
#pragma unroll
        for (int half_i = 0; half_i < 2; half_i++) {
            int r = row0 + wm * 32 + mt * 16 + (lane >> 2) + half_i * 8;
            if (r >= M) continue;
#pragma unroll
            for (int nt = 0; nt < 8; nt++) {
                int cidx = col0 + wn * 64 + nt * 8 + (lane & 3) * 2;
                float v0 = acc[mt][nt][half_i * 2 + 0] + bias[cidx];
                float v1 = acc[mt][nt][half_i * 2 + 1] + bias[cidx + 1];
                if (relu) { v0 = fmaxf(v0, 0.f); v1 = fmaxf(v1, 0.f); }
                if (write_half) {
                    __half2 hv;
                    hv.x = __float2half_rn(v0);
                    hv.y = __float2half_rn(v1);
                    *reinterpret_cast<__half2*>(outh + (size_t)r * ostride + (cidx - coff)) = hv;
                } else {
                    float2 o = make_float2(v0, v1);
                    *reinterpret_cast<float2*>(outf + (size_t)r * ostride + (cidx - coff)) = o;
                }
            }
        }
    }
#undef LOAD_STAGE
}

// ---------------- fused weight prep + q = src + pos ------------------------
__device__ __forceinline__ void wtr1(const float* __restrict__ W, __half* __restrict__ Wt,
                                     int K_, int N_, int i)
{
    int k = i / N_, n = i % N_;
    Wt[(size_t)n * K_ + k] = __float2half_rn(W[i]);
}

#define PREP_ITEMS 754304
#define ADD_ITEMS  (MTOK * DMODEL / 4)
#define PA_TOTAL   (PREP_ITEMS + ADD_ITEMS)

__global__ void prep_add_kernel(const float* __restrict__ vW, const float* __restrict__ oW,
                                const float* __restrict__ aW, const float* __restrict__ uW,
                                const float* __restrict__ f1W, const float* __restrict__ f2W,
                                const float* __restrict__ vb, const float* __restrict__ ob,
                                const float* __restrict__ ab,
                                __half* __restrict__ wtp, __half* __restrict__ wtu,
                                __half* __restrict__ wtf1, __half* __restrict__ wtf2,
                                float* __restrict__ biasp,
                                const float* __restrict__ srca, const float* __restrict__ posb,
                                float* __restrict__ q, __half* __restrict__ qh)
{
    int i = blockIdx.x * blockDim.x + threadIdx.x;
    if (i >= PREP_ITEMS) {
        int t = i - PREP_ITEMS;
        if (t >= ADD_ITEMS) return;
        float4 x = reinterpret_cast<const float4*>(srca)[t];
        float4 y = reinterpret_cast<const float4*>(posb)[t];
        x.x += y.x; x.y += y.y; x.z += y.z; x.w += y.w;
        reinterpret_cast<float4*>(q)[t] = x;
        __half2 h0 = __floats2half2_rn(x.x, x.y);
        __half2 h1 = __floats2half2_rn(x.z, x.w);
        uint2 hp;
        hp.x = *reinterpret_cast<uint32_t*>(&h0);
        hp.y = *reinterpret_cast<uint32_t*>(&h1);
        reinterpret_cast<uint2*>(qh)[t] = hp;
        return;
    }
    if (i < 65536)       { wtr1(vW, wtp, 256, 256, i); return; }
    i -= 65536;
    if (i < 65536)       { wtr1(oW, wtp + 256 * 256, 256, 256, i); return; }
    i -= 65536;
    if (i < 32768)       { wtr1(aW, wtp + 512 * 256, 256, 128, i); return; }
    i -= 32768;
    if (i < 65536)       { wtr1(uW, wtu, 256, 256, i); return; }
    i -= 65536;
    if (i < 262144)      { wtr1(f1W, wtf1, 256, 1024, i); return; }
    i -= 262144;
    if (i < 262144)      { wtr1(f2W, wtf2, 1024, 256, i); return; }
    i -= 262144;
    if (i < 256)         { biasp[i] = vb[i]; return; }
    if (i < 512)         { biasp[i] = ob[i - 256]; return; }
    if (i < 640)         { biasp[i] = ab[i - 512]; return; }
}

// ---------------- MSDA: fused softmax + float4 gathers (row-major value) ---
__global__ __launch_bounds__(256)
void msda_kernel(const __half* __restrict__ value, const float* __restrict__ offs,
                 const float* __restrict__ aw, const float* __restrict__ ref,
                 const int* __restrict__ shapes, const int* __restrict__ starts,
                 __half* __restrict__ outh)
{
    const int tok = blockIdx.x;
    const int h = threadIdx.x >> 5;
    const int lane = threadIdx.x & 31;
    const int j = lane & 15;
    const int b = tok / LIN;
    const int l = j >> 2;

    const int Hl = shapes[l * 2 + 0];
    const int Wl = shapes[l * 2 + 1];
    const int st = starts[l];
    const float fW = (float)Wl, fH = (float)Hl;
    const float rx = ref[(size_t)tok * 8 + l * 2 + 0];
    const float ry = ref[(size_t)tok * 8 + l * 2 + 1];
    const float2 off = *reinterpret_cast<const float2*>(offs + (size_t)tok * 256 + h * 32 + 2 * j);

    float logit = aw[(size_t)tok * 128 + h * 16 + j];
    float m = logit;
#pragma unroll
    for (int o = 8; o; o >>= 1) m = fmaxf(m, __shfl_xor_sync(0xffffffffu, m, o, 16));
    float e = expf(logit - m);
    float s = e;
#pragma unroll
    for (int o = 8; o; o >>= 1) s += __shfl_xor_sync(0xffffffffu, s, o, 16);
    float wgt = e / s;

    float x = (rx + off.x / fW) * fW - 0.5f;
    float y = (ry + off.y / fH) * fH - 0.5f;
    float x0f = floorf(x), y0f = floorf(y);
    float dx = x - x0f, dy = y - y0f;
    int x0 = (int)x0f, y0 = (int)y0f;
    int x1 = x0 + 1, y1 = y0 + 1;

    bool xv0 = (x0 >= 0) & (x0 < Wl);
    bool xv1 = (x1 >= 0) & (x1 < Wl);
    bool yv0 = (y0 >= 0) & (y0 < Hl);
    bool yv1 = (y1 >= 0) & (y1 < Hl);

    float w00 = (xv0 && yv0) ? wgt * (1.f - dx) * (1.f - dy) : 0.f;
    float w10 = (xv1 && yv0) ? wgt * dx * (1.f - dy) : 0.f;
    float w01 = (xv0 && yv1) ? wgt * (1.f - dx) * dy : 0.f;
    float w11 = (xv1 && yv1) ? wgt * dx * dy : 0.f;

    int cx0 = min(max(x0, 0), Wl - 1), cx1 = min(max(x1, 0), Wl - 1);
    int cy0 = min(max(y0, 0), Hl - 1), cy1 = min(max(y1, 0), Hl - 1);
    const int base = b * LIN + st;
    int i00 = base + cy0 * Wl + cx0;
    int i10 = base + cy0 * Wl + cx1;
    int i01 = base + cy1 * Wl + cx0;
    int i11 = base + cy1 * Wl + cx1;

    // ---- gather: 2 passes x 8 points, float4 (8 channels) per lane ----
    const int g = lane >> 2;
    const int c4 = lane & 3;
    const __half* vch = value + h * DH + c4 * 8;
    float acc[8] = {0.f, 0.f, 0.f, 0.f, 0.f, 0.f, 0.f, 0.f};

#pragma unroll
    for (int p = 0; p < 2; p++) {
        const int pt = p * 8 + g;
        int a00 = __shfl_sync(0xffffffffu, i00, pt);
        int a10 = __shfl_sync(0xffffffffu, i10, pt);
        int a01 = __shfl_sync(0xffffffffu, i01, pt);
        int a11 = __shfl_sync(0xffffffffu, i11, pt);
        float u00 = __shfl_sync(0xffffffffu, w00, pt);
        float u10 = __shfl_sync(0xffffffffu, w10, pt);
        float u01 = __shfl_sync(0xffffffffu, w01, pt);
        float u11 = __shfl_sync(0xffffffffu, w11, pt);

        uint4 r00 = *reinterpret_cast<const uint4*>(vch + (size_t)a00 * DMODEL);
        uint4 r10 = *reinterpret_cast<const uint4*>(vch + (size_t)a10 * DMODEL);
        uint4 r01 = *reinterpret_cast<const uint4*>(vch + (size_t)a01 * DMODEL);
        uint4 r11 = *reinterpret_cast<const uint4*>(vch + (size_t)a11 * DMODEL);

#define ACC8(rv, u) do {                                                      \
        const __half2* _h = reinterpret_cast<const __half2*>(&(rv));          \
        _Pragma("unroll")                                                     \
        for (int _k = 0; _k < 4; _k++) {                                      \
            float2 _f = __half22float2(_h[_k]);                               \
            acc[2 * _k + 0] = fmaf(u, _f.x, acc[2 * _k + 0]);                 \
            acc[2 * _k + 1] = fmaf(u, _f.y, acc[2 * _k + 1]);                 \
        } } while (0)

        ACC8(r00, u00);
        ACC8(r10, u10);
        ACC8(r01, u01);
        ACC8(r11, u11);
#undef ACC8
    }

#pragma unroll
    for (int o = 4; o <= 16; o <<= 1) {
#pragma unroll
        for (int k = 0; k < 8; k++)
            acc[k] += __shfl_xor_sync(0xffffffffu, acc[k], o);
    }

    if (lane < 4) {
        __half2 h0 = __floats2half2_rn(acc[0], acc[1]);
        __half2 h1 = __floats2half2_rn(acc[2], acc[3]);
        __half2 h2 = __floats2half2_rn(acc[4], acc[5]);
        __half2 h3 = __floats2half2_rn(acc[6], acc[7]);
        uint4 o;
        o.x = *reinterpret_cast<uint32_t*>(&h0);
        o.y = *reinterpret_cast<uint32_t*>(&h1);
        o.z = *reinterpret_cast<uint32_t*>(&h2);
        o.w = *reinterpret_cast<uint32_t*>(&h3);
        *reinterpret_cast<uint4*>(outh + (size_t)tok * DMODEL + h * DH + lane * 8) = o;
    }
}

// ---------------- warp-per-token residual add + LayerNorm ------------------
__global__ __launch_bounds__(256)
void add_ln_kernel(const float* __restrict__ a, const float* __restrict__ r,
                   const float* __restrict__ g, const float* __restrict__ bb,
                   float* __restrict__ out, __half* __restrict__ outh)
{
    const int tok = (blockIdx.x * blockDim.x + threadIdx.x) >> 5;
    const int lane = threadIdx.x & 31;
    if (tok >= MTOK) return;

    const float4* a4 = reinterpret_cast<const float4*>(a + (size_t)tok * DMODEL);
    const float4* r4 = reinterpret_cast<const float4*>(r + (size_t)tok * DMODEL);
    float4 v0 = a4[lane * 2 + 0], v1 = a4[lane * 2 + 1];
    float4 u0 = r4[lane * 2 + 0], u1 = r4[lane * 2 + 1];
    v0.x += u0.x; v0.y += u0.y; v0.z += u0.z; v0.w += u0.w;
    v1.x += u1.x; v1.y += u1.y; v1.z += u1.z; v1.w += u1.w;

    float s = v0.x + v0.y + v0.z + v0.w + v1.x + v1.y + v1.z + v1.w;
#pragma unroll
    for (int o = 16; o; o >>= 1) s += __shfl_xor_sync(0xffffffffu, s, o);
    float mean = s * (1.f / 256.f);

    float d0x = v0.x - mean, d0y = v0.y - mean, d0z = v0.z - mean, d0w = v0.w - mean;
    float d1x = v1.x - mean, d1y = v1.y - mean, d1z = v1.z - mean, d1w = v1.w - mean;
    float s2 = d0x * d0x + d0y * d0y + d0z * d0z + d0w * d0w
             + d1x * d1x + d1y * d1y + d1z * d1z + d1w * d1w;
#pragma unroll
    for (int o = 16; o; o >>= 1) s2 += __shfl_xor_sync(0xffffffffu, s2, o);
    float inv = rsqrtf(s2 * (1.f / 256.f) + 1e-5f);

    const float4* g4 = reinterpret_cast<const float4*>(g);
    const float4* b4 = reinterpret_cast<const float4*>(bb);
    float4 g0 = g4[lane * 2 + 0], g1 = g4[lane * 2 + 1];
    float4 bb0 = b4[lane * 2 + 0], bb1 = b4[lane * 2 + 1];

    float4 o0, o1;
    o0.x = d0x * inv * g0.x + bb0.x; o0.y = d0y * inv * g0.y + bb0.y;
    o0.z = d0z * inv * g0.z + bb0.z; o0.w = d0w * inv * g0.w + bb0.w;
    o1.x = d1x * inv * g1.x + bb1.x; o1.y = d1y * inv * g1.y + bb1.y;
    o1.z = d1z * inv * g1.z + bb1.z; o1.w = d1w * inv * g1.w + bb1.w;

    float4* out4 = reinterpret_cast<float4*>(out + (size_t)tok * DMODEL);
    out4[lane * 2 + 0] = o0;
    out4[lane * 2 + 1] = o1;

    if (outh) {
        __half2 h0 = __floats2half2_rn(o0.x, o0.y);
        __half2 h1 = __floats2half2_rn(o0.z, o0.w);
        __half2 h2 = __floats2half2_rn(o1.x, o1.y);
        __half2 h3 = __floats2half2_rn(o1.z, o1.w);
        uint4 hp;
        hp.x = *reinterpret_cast<uint32_t*>(&h0);
        hp.y = *reinterpret_cast<uint32_t*>(&h1);
        hp.z = *reinterpret_cast<uint32_t*>(&h2);
        hp.w = *reinterpret_cast<uint32_t*>(&h3);
        *reinterpret_cast<uint4*>(outh + (size_t)tok * DMODEL + lane * 8) = hp;
    }
}

// ---------------- launch ----------------
extern "C" void kernel_launch(void* const* d_in, const int* in_sizes, int n_in,
                              void* d_out, int out_size)
{
    const float* src    = (const float*)d_in[0];
    const float* pos    = (const float*)d_in[1];
    const float* refpts = (const float*)d_in[2];
    const int*   shapes = (const int*)  d_in[3];
    const int*   starts = (const int*)  d_in[4];
    const float* value_w = (const float*)d_in[5];
    const float* value_b = (const float*)d_in[6];
    const float* offs_w  = (const float*)d_in[7];
    const float* offs_b  = (const float*)d_in[8];
    const float* attn_w  = (const float*)d_in[9];
    const float* attn_b  = (const float*)d_in[10];
    const float* out_w   = (const float*)d_in[11];
    const float* out_b   = (const float*)d_in[12];
    const float* ln1_g   = (const float*)d_in[13];
    const float* ln1_b   = (const float*)d_in[14];
    const float* ff1_w   = (const float*)d_in[15];
    const float* ff1_b   = (const float*)d_in[16];
    const float* ff2_w   = (const float*)d_in[17];
    const float* ff2_b   = (const float*)d_in[18];
    const float* ln2_g   = (const float*)d_in[19];
    const float* ln2_b   = (const float*)d_in[20];
    float* outp = (float*)d_out;

    float *q, *offs, *aw, *src2, *x, *biasp;
    __half *qh, *value, *msdah, *xh, *ffh;
    __half *wtp, *wtu, *wtf1, *wtf2;
    cudaGetSymbolAddress((void**)&q,     g_q);
    cudaGetSymbolAddress((void**)&qh,    g_qh);
    cudaGetSymbolAddress((void**)&value, g_value);
    cudaGetSymbolAddress((void**)&offs,  g_offs);
    cudaGetSymbolAddress((void**)&aw,    g_aw);
    cudaGetSymbolAddress((void**)&msdah, g_msdah);
    cudaGetSymbolAddress((void**)&src2,  g_src2);
    cudaGetSymbolAddress((void**)&x,     g_x);
    cudaGetSymbolAddress((void**)&xh,    g_xh);
    cudaGetSymbolAddress((void**)&ffh,   g_ffh);
    cudaGetSymbolAddress((void**)&wtp,   g_wt_proj);
    cudaGetSymbolAddress((void**)&wtu,   g_wt_out);
    cudaGetSymbolAddress((void**)&wtf1,  g_wt_ff1);
    cudaGetSymbolAddress((void**)&wtf2,  g_wt_ff2);
    cudaGetSymbolAddress((void**)&biasp, g_bias_proj);

    cudaFuncSetAttribute(gemm_mma, cudaFuncAttributeMaxDynamicSharedMemorySize, GEMM_SMEM);

    const int M = MTOK;
    const int gy = (M + 127) / 128;

    // 0. fused weight prep + q = src + pos
    prep_add_kernel<<<(PA_TOTAL + 255) / 256, 256>>>(value_w, offs_w, attn_w, out_w, ff1_w, ff2_w,
                                                     value_b, offs_b, attn_b,
                                                     wtp, wtu, wtf1, wtf2, biasp,
                                                     src, pos, q, qh);

    // 1. fused projections: [value(fp16) | offs | aw] = q @ Wp^T
    gemm_mma<<<dim3(5, gy), 256, GEMM_SMEM>>>(qh, 256, wtp, 256, biasp,
                                              nullptr, value, offs, aw, M, 256, 640, 0, 2);

    // 2. deformable sampling with fused softmax
    msda_kernel<<<M, 256>>>(value, offs, aw, refpts, shapes, starts, msdah);

    // 3. output projection: src2 = msda @ out_w + out_b
    gemm_mma<<<dim3(2, gy), 256, GEMM_SMEM>>>(msdah, 256, wtu, 256, out_b,
                                              src2, nullptr, nullptr, nullptr, M, 256, 256, 0, 0);

    // 4. x = LN(q + src2)  (+ fp16 copy)
    add_ln_kernel<<<(M * 32 + 255) / 256, 256>>>(q, src2, ln1_g, ln1_b, x, xh);

    // 5. ffh = relu(x @ ff1_w + ff1_b) -> fp16
    gemm_mma<<<dim3(8, gy), 256, GEMM_SMEM>>>(xh, 256, wtf1, 256, ff1_b,
                                              nullptr, ffh, nullptr, nullptr, M, 256, 1024, 1, 1);

    // 6. f = ffh @ ff2_w + ff2_b  (into 'offs' buffer)
    gemm_mma<<<dim3(2, gy), 256, GEMM_SMEM>>>(ffh, 1024, wtf2, 1024, ff2_b,
                                              offs, nullptr, nullptr, nullptr, M, 1024, 256, 0, 0);

    // 7. out = LN(x + f)
    add_ln_kernel<<<(M * 32 + 255) / 256, 256>>>(x, offs, ln2_g, ln2_b, outp, nullptr);
}

// round 12
// speedup vs baseline: 1.0842x; 1.0214x over previous
#include <cuda_runtime.h>
#include <cuda_fp16.h>
#include <cstdint>
#include <math.h>

// ---------------- problem constants ----------------
#define Bq    4
#define LIN   13294
#define MTOK  (Bq * LIN)      // 53176
#define DMODEL 256
#define NHEAD 8
#define NLVL  4
#define NPTS  4
#define DH    32
#define DFF   1024

// ---------------- scratch (device globals) ----------------
__device__ float  g_q    [(size_t)MTOK * DMODEL];
__device__ __half g_qh   [(size_t)MTOK * DMODEL];
__device__ __half g_value[(size_t)MTOK * DMODEL];   // row-major [tok][256]
__device__ float  g_offs [(size_t)MTOK * DMODEL];
__device__ float  g_aw   [(size_t)MTOK * 128];      // raw logits
__device__ __half g_msdah[(size_t)MTOK * DMODEL];
__device__ float  g_x    [(size_t)MTOK * DMODEL];
__device__ __half g_xh   [(size_t)MTOK * DMODEL];
__device__ __half g_ffh  [(size_t)MTOK * DFF];
// weights: Wt[N, K] fp16 K-major
__device__ __half g_wt_proj[640 * 256];
__device__ __half g_wt_out [256 * 256];
__device__ __half g_wt_ff1 [1024 * 256];
__device__ __half g_wt_ff2 [256 * 1024];
__device__ float  g_bias_proj[640];

// ---------------- helpers ----------------
__device__ __forceinline__ uint32_t smem_u32(const void* p) {
    uint32_t a;
    asm("{ .reg .u64 t; cvta.to.shared.u64 t, %1; cvt.u32.u64 %0, t; }" : "=r"(a) : "l"(p));
    return a;
}
#define CP_ASYNC16(dst, src) \
    asm volatile("cp.async.cg.shared.global [%0], [%1], 16;\n" :: "r"(dst), "l"(src) : "memory")
#define CP_COMMIT() asm volatile("cp.async.commit_group;\n" ::: "memory")
#define CP_WAIT(n)  asm volatile("cp.async.wait_group %0;\n" :: "n"(n) : "memory")

__device__ __forceinline__ void ldmatrix_x4(uint32_t& r0, uint32_t& r1, uint32_t& r2, uint32_t& r3, uint32_t addr) {
    asm volatile("ldmatrix.sync.aligned.m8n8.x4.shared.b16 {%0,%1,%2,%3}, [%4];"
                 : "=r"(r0), "=r"(r1), "=r"(r2), "=r"(r3) : "r"(addr));
}
__device__ __forceinline__ void mma_f16(float* c, const uint32_t* a, const uint32_t* b) {
    asm volatile("mma.sync.aligned.m16n8k16.row.col.f32.f16.f16.f32 "
                 "{%0,%1,%2,%3}, {%4,%5,%6,%7}, {%8,%9}, {%0,%1,%2,%3};"
                 : "+f"(c[0]), "+f"(c[1]), "+f"(c[2]), "+f"(c[3])
                 : "r"(a[0]), "r"(a[1]), "r"(a[2]), "r"(a[3]), "r"(b[0]), "r"(b[1]));
}

#define PADS 40
#define STAGE_ELEMS (128 * PADS)
#define NSTAGE 4
#define GEMM_SMEM (2 * NSTAGE * STAGE_ELEMS * 2)   // 81920 bytes

// ---------------- fp16 warp-MMA GEMM (pair-buffered) — proj / ff1 ----------
// mode 1: Ch fp16 [M,N].
// mode 2: cols 0-255 -> Ch fp16 (value); 256-511 -> C2 (fp32,256); 512-639 -> C3 (fp32,128).
__global__ __launch_bounds__(256, 2)
void gemm_mma(const __half* __restrict__ A, int lda,
              const __half* __restrict__ B, int ldb,
              const float* __restrict__ bias,
              float* __restrict__ Cf, __half* __restrict__ Ch,
              float* __restrict__ C2, float* __restrict__ C3,
              int M, int K, int N, int relu, int mode)
{
    extern __shared__ __align__(16) __half dynsmem[];

    const int tid  = threadIdx.x;
    const int wid  = tid >> 5;
    const int lane = tid & 31;
    const int wm   = wid & 3;
    const int wn   = wid >> 2;
    const int row0 = blockIdx.y * 128;
    const int col0 = blockIdx.x * 128;

    const uint32_t sbase = smem_u32(dynsmem);
    const int NC2 = K >> 6;

    float acc[2][8][4];
#pragma unroll
    for (int i = 0; i < 2; i++)
#pragma unroll
        for (int j = 0; j < 8; j++)
#pragma unroll
            for (int t = 0; t < 4; t++) acc[i][j][t] = 0.f;

#define LOAD_STAGE(buf, cc) do {                                              \
        int _kc = (cc) << 5;                                                  \
        uint32_t _dA = sbase + (buf) * (STAGE_ELEMS * 2);                     \
        uint32_t _dB = sbase + (NSTAGE + (buf)) * (STAGE_ELEMS * 2);          \
        _Pragma("unroll")                                                     \
        for (int _i = 0; _i < 2; ++_i) {                                      \
            int _c = tid + _i * 256;                                          \
            int _r = _c >> 2, _k8 = _c & 3;                                   \
            int _gr = row0 + _r; if (_gr >= M) _gr = M - 1;                   \
            CP_ASYNC16(_dA + (_r * PADS + _k8 * 8) * 2,                       \
                       A + (size_t)_gr * lda + _kc + _k8 * 8);                \
        }                                                                     \
        _Pragma("unroll")                                                     \
        for (int _i = 0; _i < 2; ++_i) {                                      \
            int _c = tid + _i * 256;                                          \
            int _r = _c >> 2, _k8 = _c & 3;                                   \
            CP_ASYNC16(_dB + (_r * PADS + _k8 * 8) * 2,                       \
                       B + (size_t)(col0 + _r) * ldb + _kc + _k8 * 8);        \
        }                                                                     \
    } while (0)

    LOAD_STAGE(0, 0);
    LOAD_STAGE(1, 1);
    CP_COMMIT();

    for (int c = 0; c < NC2; ++c) {
        CP_WAIT(0);
        __syncthreads();

        if (c + 1 < NC2) {
            const int pb = ((c + 1) & 1) << 1;
            LOAD_STAGE(pb, 2 * (c + 1));
            LOAD_STAGE(pb + 1, 2 * (c + 1) + 1);
        }
        CP_COMMIT();

        const int cb = (c & 1) << 1;
#pragma unroll
        for (int hs = 0; hs < 2; hs++) {
            const uint32_t baseA = sbase + (cb + hs) * (STAGE_ELEMS * 2);
            const uint32_t baseB = sbase + (NSTAGE + cb + hs) * (STAGE_ELEMS * 2);
#pragma unroll
            for (int kk = 0; kk < 32; kk += 16) {
                uint32_t a[2][4];
#pragma unroll
                for (int mt = 0; mt < 2; mt++) {
                    int r = wm * 32 + mt * 16 + (lane & 15);
                    int kc = kk + ((lane & 16) ? 8 : 0);
                    ldmatrix_x4(a[mt][0], a[mt][1], a[mt][2], a[mt][3],
                                baseA + (r * PADS + kc) * 2);
                }
                uint32_t b[8][2];
#pragma unroll
                for (int np = 0; np < 4; np++) {
                    int n = wn * 64 + np * 16 + (lane & 7) + ((lane & 16) ? 8 : 0);
                    int kc = kk + ((lane & 8) ? 8 : 0);
                    ldmatrix_x4(b[2 * np][0], b[2 * np][1], b[2 * np + 1][0], b[2 * np + 1][1],
                                baseB + (n * PADS + kc) * 2);
                }
#pragma unroll
                for (int mt = 0; mt < 2; mt++)
#pragma unroll
                    for (int nt = 0; nt < 8; nt++)
                        mma_f16(acc[mt][nt], a[mt], b[nt]);
            }
        }
    }

    // ---- epilogue ----
    float* outf = Cf;
    __half* outh = Ch;
    int ostride = N, coff = 0;
    int write_half = (mode == 1);
    if (mode == 2) {
        if (col0 < 256)      { outh = Ch; ostride = 256; coff = 0; write_half = 1; }
        else if (col0 < 512) { outf = C2; ostride = 256; coff = 256; }
        else                 { outf = C3; ostride = 128; coff = 512; }
    }

#pragma unroll
    for (int mt = 0; mt < 2; mt++) {
#pragma unroll
        for (int half_i = 0; half_i < 2; half_i++) {
            int r = row0 + wm * 32 + mt * 16 + (lane >> 2) + half_i * 8;
            if (r >= M) continue;
#pragma unroll
            for (int nt = 0; nt < 8; nt++) {
                int cidx = col0 + wn * 64 + nt * 8 + (lane & 3) * 2;
                float v0 = acc[mt][nt][half_i * 2 + 0] + bias[cidx];
                float v1 = acc[mt][nt][half_i * 2 + 1] + bias[cidx + 1];
                if (relu) { v0 = fmaxf(v0, 0.f); v1 = fmaxf(v1, 0.f); }
                if (write_half) {
                    __half2 hv;
                    hv.x = __float2half_rn(v0);
                    hv.y = __float2half_rn(v1);
                    *reinterpret_cast<__half2*>(outh + (size_t)r * ostride + (cidx - coff)) = hv;
                } else {
                    float2 o = make_float2(v0, v1);
                    *reinterpret_cast<float2*>(outf + (size_t)r * ostride + (cidx - coff)) = o;
                }
            }
        }
    }
#undef LOAD_STAGE
}

// ---------------- GEMM + residual + LayerNorm fused (N = 256 fixed) --------
// tile 128x256, 512 threads (4 wm x 4 wn warps, warp tile 32x64).
// out = LN(residual + A@B^T + bias) * g + beta ; optional fp16 copy.
#define A_ST (128 * PADS * 2)          // bytes per A stage
#define B_ST (256 * PADS * 2)          // bytes per B stage
#define GEMMLN_SMEM (NSTAGE * (A_ST + B_ST))   // 122880 bytes

__global__ __launch_bounds__(512, 1)
void gemm_ln(const __half* __restrict__ A, int lda,
             const __half* __restrict__ B,
             const float* __restrict__ bias,
             const float* __restrict__ resid,
             const float* __restrict__ lng, const float* __restrict__ lnb,
             float* __restrict__ out, __half* __restrict__ outh,
             int M, int K)
{
    extern __shared__ __align__(16) __half dynsmem[];

    const int tid  = threadIdx.x;
    const int wid  = tid >> 5;
    const int lane = tid & 31;
    const int wm   = wid & 3;
    const int wn   = wid >> 2;          // 0..3 (64 cols each)
    const int row0 = blockIdx.y * 128;

    const uint32_t sbase = smem_u32(dynsmem);
    const uint32_t sbB = sbase + NSTAGE * A_ST;
    const int NC2 = K >> 6;

    float acc[2][8][4];
#pragma unroll
    for (int i = 0; i < 2; i++)
#pragma unroll
        for (int j = 0; j < 8; j++)
#pragma unroll
            for (int t = 0; t < 4; t++) acc[i][j][t] = 0.f;

#define LOAD_STAGE_LN(buf, cc) do {                                           \
        int _kc = (cc) << 5;                                                  \
        uint32_t _dA = sbase + (buf) * A_ST;                                  \
        uint32_t _dB = sbB + (buf) * B_ST;                                    \
        {   /* A: 512 chunks, 1 per thread */                                 \
            int _r = tid >> 2, _k8 = tid & 3;                                 \
            int _gr = row0 + _r; if (_gr >= M) _gr = M - 1;                   \
            CP_ASYNC16(_dA + (_r * PADS + _k8 * 8) * 2,                       \
                       A + (size_t)_gr * lda + _kc + _k8 * 8);                \
        }                                                                     \
        _Pragma("unroll")                                                     \
        for (int _i = 0; _i < 2; ++_i) {  /* B: 1024 chunks, 2 per thread */  \
            int _c = tid + _i * 512;                                          \
            int _r = _c >> 2, _k8 = _c & 3;                                   \
            CP_ASYNC16(_dB + (_r * PADS + _k8 * 8) * 2,                       \
                       B + (size_t)_r * K + _kc + _k8 * 8);                   \
        }                                                                     \
    } while (0)

    LOAD_STAGE_LN(0, 0);
    LOAD_STAGE_LN(1, 1);
    CP_COMMIT();

    for (int c = 0; c < NC2; ++c) {
        CP_WAIT(0);
        __syncthreads();

        if (c + 1 < NC2) {
            const int pb = ((c + 1) & 1) << 1;
            LOAD_STAGE_LN(pb, 2 * (c + 1));
            LOAD_STAGE_LN(pb + 1, 2 * (c + 1) + 1);
        }
        CP_COMMIT();

        const int cb = (c & 1) << 1;
#pragma unroll
        for (int hs = 0; hs < 2; hs++) {
            const uint32_t baseA = sbase + (cb + hs) * A_ST;
            const uint32_t baseB = sbB + (cb + hs) * B_ST;
#pragma unroll
            for (int kk = 0; kk < 32; kk += 16) {
                uint32_t a[2][4];
#pragma unroll
                for (int mt = 0; mt < 2; mt++) {
                    int r = wm * 32 + mt * 16 + (lane & 15);
                    int kc = kk + ((lane & 16) ? 8 : 0);
                    ldmatrix_x4(a[mt][0], a[mt][1], a[mt][2], a[mt][3],
                                baseA + (r * PADS + kc) * 2);
                }
                uint32_t b[8][2];
#pragma unroll
                for (int np = 0; np < 4; np++) {
                    int n = wn * 64 + np * 16 + (lane & 7) + ((lane & 16) ? 8 : 0);
                    int kc = kk + ((lane & 8) ? 8 : 0);
                    ldmatrix_x4(b[2 * np][0], b[2 * np][1], b[2 * np + 1][0], b[2 * np + 1][1],
                                baseB + (n * PADS + kc) * 2);
                }
#pragma unroll
                for (int mt = 0; mt < 2; mt++)
#pragma unroll
                    for (int nt = 0; nt < 8; nt++)
                        mma_f16(acc[mt][nt], a[mt], b[nt]);
            }
        }
    }

    // ---- fused epilogue: bias + residual + per-row LayerNorm ----
    __syncthreads();                       // stages done; reuse smem
    float* red = reinterpret_cast<float*>(dynsmem);   // [4 wn][128 rows][2]

    // pass 1: v = acc + bias + residual; per-row partial sums
#pragma unroll
    for (int mt = 0; mt < 2; mt++) {
#pragma unroll
        for (int hf = 0; hf < 2; hf++) {
            int lr = wm * 32 + mt * 16 + (lane >> 2) + hf * 8;   // local row
            int r = row0 + lr;
            int rc = (r < M) ? r : (M - 1);
            float s1 = 0.f, s2 = 0.f;
#pragma unroll
            for (int nt = 0; nt < 8; nt++) {
                int cidx = wn * 64 + nt * 8 + (lane & 3) * 2;
                float2 res = *reinterpret_cast<const float2*>(resid + (size_t)rc * 256 + cidx);
                float2 bv = *reinterpret_cast<const float2*>(bias + cidx);
                float v0 = acc[mt][nt][hf * 2 + 0] + bv.x + res.x;
                float v1 = acc[mt][nt][hf * 2 + 1] + bv.y + res.y;
                acc[mt][nt][hf * 2 + 0] = v0;
                acc[mt][nt][hf * 2 + 1] = v1;
                s1 += v0 + v1;
                s2 += v0 * v0 + v1 * v1;
            }
            s1 += __shfl_xor_sync(0xffffffffu, s1, 1);
            s2 += __shfl_xor_sync(0xffffffffu, s2, 1);
            s1 += __shfl_xor_sync(0xffffffffu, s1, 2);
            s2 += __shfl_xor_sync(0xffffffffu, s2, 2);
            if ((lane & 3) == 0) {
                red[(wn * 128 + lr) * 2 + 0] = s1;
                red[(wn * 128 + lr) * 2 + 1] = s2;
            }
        }
    }
    __syncthreads();

    // pass 2: normalize + write
#pragma unroll
    for (int mt = 0; mt < 2; mt++) {
#pragma unroll
        for (int hf = 0; hf < 2; hf++) {
            int lr = wm * 32 + mt * 16 + (lane >> 2) + hf * 8;
            int r = row0 + lr;
            if (r >= M) continue;
            float t1 = red[(0 * 128 + lr) * 2 + 0] + red[(1 * 128 + lr) * 2 + 0]
                     + red[(2 * 128 + lr) * 2 + 0] + red[(3 * 128 + lr) * 2 + 0];
            float t2 = red[(0 * 128 + lr) * 2 + 1] + red[(1 * 128 + lr) * 2 + 1]
                     + red[(2 * 128 + lr) * 2 + 1] + red[(3 * 128 + lr) * 2 + 1];
            float mean = t1 * (1.f / 256.f);
            float var = t2 * (1.f / 256.f) - mean * mean;
            float inv = rsqrtf(var + 1e-5f);
#pragma unroll
            for (int nt = 0; nt < 8; nt++) {
                int cidx = wn * 64 + nt * 8 + (lane & 3) * 2;
                float2 gv = *reinterpret_cast<const float2*>(lng + cidx);
                float2 bv = *reinterpret_cast<const float2*>(lnb + cidx);
                float o0 = (acc[mt][nt][hf * 2 + 0] - mean) * inv * gv.x + bv.x;
                float o1 = (acc[mt][nt][hf * 2 + 1] - mean) * inv * gv.y + bv.y;
                *reinterpret_cast<float2*>(out + (size_t)r * 256 + cidx) = make_float2(o0, o1);
                if (outh) {
                    __half2 hv;
                    hv.x = __float2half_rn(o0);
                    hv.y = __float2half_rn(o1);
                    *reinterpret_cast<__half2*>(outh + (size_t)r * 256 + cidx) = hv;
                }
            }
        }
    }
#undef LOAD_STAGE_LN
}

// ---------------- fused weight prep + q = src + pos ------------------------
__device__ __forceinline__ void wtr1(const float* __restrict__ W, __half* __restrict__ Wt,
                                     int K_, int N_, int i)
{
    int k = i / N_, n = i % N_;
    Wt[(size_t)n * K_ + k] = __float2half_rn(W[i]);
}

#define PREP_ITEMS 754304
#define ADD_ITEMS  (MTOK * DMODEL / 4)
#define PA_TOTAL   (PREP_ITEMS + ADD_ITEMS)

__global__ void prep_add_kernel(const float* __restrict__ vW, const float* __restrict__ oW,
                                const float* __restrict__ aW, const float* __restrict__ uW,
                                const float* __restrict__ f1W, const float* __restrict__ f2W,
                                const float* __restrict__ vb, const float* __restrict__ ob,
                                const float* __restrict__ ab,
                                __half* __restrict__ wtp, __half* __restrict__ wtu,
                                __half* __restrict__ wtf1, __half* __restrict__ wtf2,
                                float* __restrict__ biasp,
                                const float* __restrict__ srca, const float* __restrict__ posb,
                                float* __restrict__ q, __half* __restrict__ qh)
{
    int i = blockIdx.x * blockDim.x + threadIdx.x;
    if (i >= PREP_ITEMS) {
        int t = i - PREP_ITEMS;
        if (t >= ADD_ITEMS) return;
        float4 x = reinterpret_cast<const float4*>(srca)[t];
        float4 y = reinterpret_cast<const float4*>(posb)[t];
        x.x += y.x; x.y += y.y; x.z += y.z; x.w += y.w;
        reinterpret_cast<float4*>(q)[t] = x;
        __half2 h0 = __floats2half2_rn(x.x, x.y);
        __half2 h1 = __floats2half2_rn(x.z, x.w);
        uint2 hp;
        hp.x = *reinterpret_cast<uint32_t*>(&h0);
        hp.y = *reinterpret_cast<uint32_t*>(&h1);
        reinterpret_cast<uint2*>(qh)[t] = hp;
        return;
    }
    if (i < 65536)       { wtr1(vW, wtp, 256, 256, i); return; }
    i -= 65536;
    if (i < 65536)       { wtr1(oW, wtp + 256 * 256, 256, 256, i); return; }
    i -= 65536;
    if (i < 32768)       { wtr1(aW, wtp + 512 * 256, 256, 128, i); return; }
    i -= 32768;
    if (i < 65536)       { wtr1(uW, wtu, 256, 256, i); return; }
    i -= 65536;
    if (i < 262144)      { wtr1(f1W, wtf1, 256, 1024, i); return; }
    i -= 262144;
    if (i < 262144)      { wtr1(f2W, wtf2, 1024, 256, i); return; }
    i -= 262144;
    if (i < 256)         { biasp[i] = vb[i]; return; }
    if (i < 512)         { biasp[i] = ob[i - 256]; return; }
    if (i < 640)         { biasp[i] = ab[i - 512]; return; }
}

// ---------------- MSDA: fused softmax + float4 gathers (row-major value) ---
__global__ __launch_bounds__(256)
void msda_kernel(const __half* __restrict__ value, const float* __restrict__ offs,
                 const float* __restrict__ aw, const float* __restrict__ ref,
                 const int* __restrict__ shapes, const int* __restrict__ starts,
                 __half* __restrict__ outh)
{
    const int tok = blockIdx.x;
    const int h = threadIdx.x >> 5;
    const int lane = threadIdx.x & 31;
    const int j = lane & 15;
    const int b = tok / LIN;
    const int l = j >> 2;

    const int Hl = shapes[l * 2 + 0];
    const int Wl = shapes[l * 2 + 1];
    const int st = starts[l];
    const float fW = (float)Wl, fH = (float)Hl;
    const float rx = ref[(size_t)tok * 8 + l * 2 + 0];
    const float ry = ref[(size_t)tok * 8 + l * 2 + 1];
    const float2 off = *reinterpret_cast<const float2*>(offs + (size_t)tok * 256 + h * 32 + 2 * j);

    float logit = aw[(size_t)tok * 128 + h * 16 + j];
    float m = logit;
#pragma unroll
    for (int o = 8; o; o >>= 1) m = fmaxf(m, __shfl_xor_sync(0xffffffffu, m, o, 16));
    float e = expf(logit - m);
    float s = e;
#pragma unroll
    for (int o = 8; o; o >>= 1) s += __shfl_xor_sync(0xffffffffu, s, o, 16);
    float wgt = e / s;

    float x = (rx + off.x / fW) * fW - 0.5f;
    float y = (ry + off.y / fH) * fH - 0.5f;
    float x0f = floorf(x), y0f = floorf(y);
    float dx = x - x0f, dy = y - y0f;
    int x0 = (int)x0f, y0 = (int)y0f;
    int x1 = x0 + 1, y1 = y0 + 1;

    bool xv0 = (x0 >= 0) & (x0 < Wl);
    bool xv1 = (x1 >= 0) & (x1 < Wl);
    bool yv0 = (y0 >= 0) & (y0 < Hl);
    bool yv1 = (y1 >= 0) & (y1 < Hl);

    float w00 = (xv0 && yv0) ? wgt * (1.f - dx) * (1.f - dy) : 0.f;
    float w10 = (xv1 && yv0) ? wgt * dx * (1.f - dy) : 0.f;
    float w01 = (xv0 && yv1) ? wgt * (1.f - dx) * dy : 0.f;
    float w11 = (xv1 && yv1) ? wgt * dx * dy : 0.f;

    int cx0 = min(max(x0, 0), Wl - 1), cx1 = min(max(x1, 0), Wl - 1);
    int cy0 = min(max(y0, 0), Hl - 1), cy1 = min(max(y1, 0), Hl - 1);
    const int base = b * LIN + st;
    int i00 = base + cy0 * Wl + cx0;
    int i10 = base + cy0 * Wl + cx1;
    int i01 = base + cy1 * Wl + cx0;
    int i11 = base + cy1 * Wl + cx1;

    const int g = lane >> 2;
    const int c4 = lane & 3;
    const __half* vch = value + h * DH + c4 * 8;
    float acc[8] = {0.f, 0.f, 0.f, 0.f, 0.f, 0.f, 0.f, 0.f};

#pragma unroll
    for (int p = 0; p < 2; p++) {
        const int pt = p * 8 + g;
        int a00 = __shfl_sync(0xffffffffu, i00, pt);
        int a10 = __shfl_sync(0xffffffffu, i10, pt);
        int a01 = __shfl_sync(0xffffffffu, i01, pt);
        int a11 = __shfl_sync(0xffffffffu, i11, pt);
        float u00 = __shfl_sync(0xffffffffu, w00, pt);
        float u10 = __shfl_sync(0xffffffffu, w10, pt);
        float u01 = __shfl_sync(0xffffffffu, w01, pt);
        float u11 = __shfl_sync(0xffffffffu, w11, pt);

        uint4 r00 = *reinterpret_cast<const uint4*>(vch + (size_t)a00 * DMODEL);
        uint4 r10 = *reinterpret_cast<const uint4*>(vch + (size_t)a10 * DMODEL);
        uint4 r01 = *reinterpret_cast<const uint4*>(vch + (size_t)a01 * DMODEL);
        uint4 r11 = *reinterpret_cast<const uint4*>(vch + (size_t)a11 * DMODEL);

#define ACC8(rv, u) do {                                                      \
        const __half2* _h = reinterpret_cast<const __half2*>(&(rv));          \
        _Pragma("unroll")                                                     \
        for (int _k = 0; _k < 4; _k++) {                                      \
            float2 _f = __half22float2(_h[_k]);                               \
            acc[2 * _k + 0] = fmaf(u, _f.x, acc[2 * _k + 0]);                 \
            acc[2 * _k + 1] = fmaf(u, _f.y, acc[2 * _k + 1]);                 \
        } } while (0)

        ACC8(r00, u00);
        ACC8(r10, u10);
        ACC8(r01, u01);
        ACC8(r11, u11);
#undef ACC8
    }

#pragma unroll
    for (int o = 4; o <= 16; o <<= 1) {
#pragma unroll
        for (int k = 0; k < 8; k++)
            acc[k] += __shfl_xor_sync(0xffffffffu, acc[k], o);
    }

    if (lane < 4) {
        __half2 h0 = __floats2half2_rn(acc[0], acc[1]);
        __half2 h1 = __floats2half2_rn(acc[2], acc[3]);
        __half2 h2 = __floats2half2_rn(acc[4], acc[5]);
        __half2 h3 = __floats2half2_rn(acc[6], acc[7]);
        uint4 o;
        o.x = *reinterpret_cast<uint32_t*>(&h0);
        o.y = *reinterpret_cast<uint32_t*>(&h1);
        o.z = *reinterpret_cast<uint32_t*>(&h2);
        o.w = *reinterpret_cast<uint32_t*>(&h3);
        *reinterpret_cast<uint4*>(outh + (size_t)tok * DMODEL + h * DH + lane * 8) = o;
    }
}

// ---------------- launch ----------------
extern "C" void kernel_launch(void* const* d_in, const int* in_sizes, int n_in,
                              void* d_out, int out_size)
{
    const float* src    = (const float*)d_in[0];
    const float* pos    = (const float*)d_in[1];
    const float* refpts = (const float*)d_in[2];
    const int*   shapes = (const int*)  d_in[3];
    const int*   starts = (const int*)  d_in[4];
    const float* value_w = (const float*)d_in[5];
    const float* value_b = (const float*)d_in[6];
    const float* offs_w  = (const float*)d_in[7];
    const float* offs_b  = (const float*)d_in[8];
    const float* attn_w  = (const float*)d_in[9];
    const float* attn_b  = (const float*)d_in[10];
    const float* out_w   = (const float*)d_in[11];
    const float* out_b   = (const float*)d_in[12];
    const float* ln1_g   = (const float*)d_in[13];
    const float* ln1_b   = (const float*)d_in[14];
    const float* ff1_w   = (const float*)d_in[15];
    const float* ff1_b   = (const float*)d_in[16];
    const float* ff2_w   = (const float*)d_in[17];
    const float* ff2_b   = (const float*)d_in[18];
    const float* ln2_g   = (const float*)d_in[19];
    const float* ln2_b   = (const float*)d_in[20];
    float* outp = (float*)d_out;

    float *q, *offs, *aw, *x, *biasp;
    __half *qh, *value, *msdah, *xh, *ffh;
    __half *wtp, *wtu, *wtf1, *wtf2;
    cudaGetSymbolAddress((void**)&q,     g_q);
    cudaGetSymbolAddress((void**)&qh,    g_qh);
    cudaGetSymbolAddress((void**)&value, g_value);
    cudaGetSymbolAddress((void**)&offs,  g_offs);
    cudaGetSymbolAddress((void**)&aw,    g_aw);
    cudaGetSymbolAddress((void**)&msdah, g_msdah);
    cudaGetSymbolAddress((void**)&x,     g_x);
    cudaGetSymbolAddress((void**)&xh,    g_xh);
    cudaGetSymbolAddress((void**)&ffh,   g_ffh);
    cudaGetSymbolAddress((void**)&wtp,   g_wt_proj);
    cudaGetSymbolAddress((void**)&wtu,   g_wt_out);
    cudaGetSymbolAddress((void**)&wtf1,  g_wt_ff1);
    cudaGetSymbolAddress((void**)&wtf2,  g_wt_ff2);
    cudaGetSymbolAddress((void**)&biasp, g_bias_proj);

    cudaFuncSetAttribute(gemm_mma, cudaFuncAttributeMaxDynamicSharedMemorySize, GEMM_SMEM);
    cudaFuncSetAttribute(gemm_ln, cudaFuncAttributeMaxDynamicSharedMemorySize, GEMMLN_SMEM);

    const int M = MTOK;
    const int gy = (M + 127) / 128;

    // 0. fused weight prep + q = src + pos
    prep_add_kernel<<<(PA_TOTAL + 255) / 256, 256>>>(value_w, offs_w, attn_w, out_w, ff1_w, ff2_w,
                                                     value_b, offs_b, attn_b,
                                                     wtp, wtu, wtf1, wtf2, biasp,
                                                     src, pos, q, qh);

    // 1. fused projections: [value(fp16) | offs | aw] = q @ Wp^T
    gemm_mma<<<dim3(5, gy), 256, GEMM_SMEM>>>(qh, 256, wtp, 256, biasp,
                                              nullptr, value, offs, aw, M, 256, 640, 0, 2);

    // 2. deformable sampling with fused softmax
    msda_kernel<<<M, 256>>>(value, offs, aw, refpts, shapes, starts, msdah);

    // 3. x = LN(q + msda @ out_w + out_b)  (+ fp16 copy xh)   [fused]
    gemm_ln<<<dim3(1, gy), 512, GEMMLN_SMEM>>>(msdah, 256, wtu, out_b,
                                               q, ln1_g, ln1_b, x, xh, M, 256);

    // 4. ffh = relu(x @ ff1_w + ff1_b) -> fp16
    gemm_mma<<<dim3(8, gy), 256, GEMM_SMEM>>>(xh, 256, wtf1, 256, ff1_b,
                                              nullptr, ffh, nullptr, nullptr, M, 256, 1024, 1, 1);

    // 5. out = LN(x + ffh @ ff2_w + ff2_b)   [fused]
    gemm_ln<<<dim3(1, gy), 512, GEMMLN_SMEM>>>(ffh, 1024, wtf2, ff2_b,
                                               x, ln2_g, ln2_b, outp, nullptr, M, 1024);
}

// round 13
// speedup vs baseline: 1.1205x; 1.0335x over previous
#include <cuda_runtime.h>
#include <cuda_fp16.h>
#include <cstdint>
#include <math.h>

// ---------------- problem constants ----------------
#define Bq    4
#define LIN   13294
#define MTOK  (Bq * LIN)      // 53176
#define DMODEL 256
#define NHEAD 8
#define NLVL  4
#define NPTS  4
#define DH    32
#define DFF   1024

// ---------------- scratch (device globals) ----------------
__device__ __half g_qh   [(size_t)MTOK * DMODEL];
__device__ __half g_value[(size_t)MTOK * DMODEL];   // row-major [tok][256]
__device__ float  g_offs [(size_t)MTOK * DMODEL];
__device__ float  g_aw   [(size_t)MTOK * 128];      // raw logits
__device__ __half g_msdah[(size_t)MTOK * DMODEL];
__device__ __half g_xh   [(size_t)MTOK * DMODEL];
__device__ __half g_ffh  [(size_t)MTOK * DFF];
// weights: Wt[N, K] fp16 K-major
__device__ __half g_wt_proj[640 * 256];
__device__ __half g_wt_out [256 * 256];
__device__ __half g_wt_ff1 [1024 * 256];
__device__ __half g_wt_ff2 [256 * 1024];
__device__ float  g_bias_proj[640];

// ---------------- helpers ----------------
__device__ __forceinline__ uint32_t smem_u32(const void* p) {
    uint32_t a;
    asm("{ .reg .u64 t; cvta.to.shared.u64 t, %1; cvt.u32.u64 %0, t; }" : "=r"(a) : "l"(p));
    return a;
}
#define CP_ASYNC16(dst, src) \
    asm volatile("cp.async.cg.shared.global [%0], [%1], 16;\n" :: "r"(dst), "l"(src) : "memory")
#define CP_COMMIT() asm volatile("cp.async.commit_group;\n" ::: "memory")
#define CP_WAIT(n)  asm volatile("cp.async.wait_group %0;\n" :: "n"(n) : "memory")

__device__ __forceinline__ void ldmatrix_x4(uint32_t& r0, uint32_t& r1, uint32_t& r2, uint32_t& r3, uint32_t addr) {
    asm volatile("ldmatrix.sync.aligned.m8n8.x4.shared.b16 {%0,%1,%2,%3}, [%4];"
                 : "=r"(r0), "=r"(r1), "=r"(r2), "=r"(r3) : "r"(addr));
}
__device__ __forceinline__ void mma_f16(float* c, const uint32_t* a, const uint32_t* b) {
    asm volatile("mma.sync.aligned.m16n8k16.row.col.f32.f16.f16.f32 "
                 "{%0,%1,%2,%3}, {%4,%5,%6,%7}, {%8,%9}, {%0,%1,%2,%3};"
                 : "+f"(c[0]), "+f"(c[1]), "+f"(c[2]), "+f"(c[3])
                 : "r"(a[0]), "r"(a[1]), "r"(a[2]), "r"(a[3]), "r"(b[0]), "r"(b[1]));
}

#define PADS 40
#define STAGE_ELEMS (128 * PADS)
#define NSTAGE 4
#define GEMM_SMEM (2 * NSTAGE * STAGE_ELEMS * 2)   // 81920 bytes

// ---------------- fp16 warp-MMA GEMM (pair-buffered) — proj / ff1 ----------
// mode 1: Ch fp16 [M,N].
// mode 2: cols 0-255 -> Ch fp16 (value); 256-511 -> C2 (fp32,256); 512-639 -> C3 (fp32,128).
__global__ __launch_bounds__(256, 2)
void gemm_mma(const __half* __restrict__ A, int lda,
              const __half* __restrict__ B, int ldb,
              const float* __restrict__ bias,
              float* __restrict__ Cf, __half* __restrict__ Ch,
              float* __restrict__ C2, float* __restrict__ C3,
              int M, int K, int N, int relu, int mode)
{
    extern __shared__ __align__(16) __half dynsmem[];

    const int tid  = threadIdx.x;
    const int wid  = tid >> 5;
    const int lane = tid & 31;
    const int wm   = wid & 3;
    const int wn   = wid >> 2;
    const int row0 = blockIdx.y * 128;
    const int col0 = blockIdx.x * 128;

    const uint32_t sbase = smem_u32(dynsmem);
    const int NC2 = K >> 6;

    float acc[2][8][4];
#pragma unroll
    for (int i = 0; i < 2; i++)
#pragma unroll
        for (int j = 0; j < 8; j++)
#pragma unroll
            for (int t = 0; t < 4; t++) acc[i][j][t] = 0.f;

#define LOAD_STAGE(buf, cc) do {                                              \
        int _kc = (cc) << 5;                                                  \
        uint32_t _dA = sbase + (buf) * (STAGE_ELEMS * 2);                     \
        uint32_t _dB = sbase + (NSTAGE + (buf)) * (STAGE_ELEMS * 2);          \
        _Pragma("unroll")                                                     \
        for (int _i = 0; _i < 2; ++_i) {                                      \
            int _c = tid + _i * 256;                                          \
            int _r = _c >> 2, _k8 = _c & 3;                                   \
            int _gr = row0 + _r; if (_gr >= M) _gr = M - 1;                   \
            CP_ASYNC16(_dA + (_r * PADS + _k8 * 8) * 2,                       \
                       A + (size_t)_gr * lda + _kc + _k8 * 8);                \
        }                                                                     \
        _Pragma("unroll")                                                     \
        for (int _i = 0; _i < 2; ++_i) {                                      \
            int _c = tid + _i * 256;                                          \
            int _r = _c >> 2, _k8 = _c & 3;                                   \
            CP_ASYNC16(_dB + (_r * PADS + _k8 * 8) * 2,                       \
                       B + (size_t)(col0 + _r) * ldb + _kc + _k8 * 8);        \
        }                                                                     \
    } while (0)

    LOAD_STAGE(0, 0);
    LOAD_STAGE(1, 1);
    CP_COMMIT();

    for (int c = 0; c < NC2; ++c) {
        CP_WAIT(0);
        __syncthreads();

        if (c + 1 < NC2) {
            const int pb = ((c + 1) & 1) << 1;
            LOAD_STAGE(pb, 2 * (c + 1));
            LOAD_STAGE(pb + 1, 2 * (c + 1) + 1);
        }
        CP_COMMIT();

        const int cb = (c & 1) << 1;
#pragma unroll
        for (int hs = 0; hs < 2; hs++) {
            const uint32_t baseA = sbase + (cb + hs) * (STAGE_ELEMS * 2);
            const uint32_t baseB = sbase + (NSTAGE + cb + hs) * (STAGE_ELEMS * 2);
#pragma unroll
            for (int kk = 0; kk < 32; kk += 16) {
                uint32_t a[2][4];
#pragma unroll
                for (int mt = 0; mt < 2; mt++) {
                    int r = wm * 32 + mt * 16 + (lane & 15);
                    int kc = kk + ((lane & 16) ? 8 : 0);
                    ldmatrix_x4(a[mt][0], a[mt][1], a[mt][2], a[mt][3],
                                baseA + (r * PADS + kc) * 2);
                }
                uint32_t b[8][2];
#pragma unroll
                for (int np = 0; np < 4; np++) {
                    int n = wn * 64 + np * 16 + (lane & 7) + ((lane & 16) ? 8 : 0);
                    int kc = kk + ((lane & 8) ? 8 : 0);
                    ldmatrix_x4(b[2 * np][0], b[2 * np][1], b[2 * np + 1][0], b[2 * np + 1][1],
                                baseB + (n * PADS + kc) * 2);
                }
#pragma unroll
                for (int mt = 0; mt < 2; mt++)
#pragma unroll
                    for (int nt = 0; nt < 8; nt++)
                        mma_f16(acc[mt][nt], a[mt], b[nt]);
            }
        }
    }

    // ---- epilogue ----
    float* outf = Cf;
    __half* outh = Ch;
    int ostride = N, coff = 0;
    int write_half = (mode == 1);
    if (mode == 2) {
        if (col0 < 256)      { outh = Ch; ostride = 256; coff = 0; write_half = 1; }
        else if (col0 < 512) { outf = C2; ostride = 256; coff = 256; }
        else                 { outf = C3; ostride = 128; coff = 512; }
    }

#pragma unroll
    for (int mt = 0; mt < 2; mt++) {
#pragma unroll
        for (int half_i = 0; half_i < 2; half_i++) {
            int r = row0 + wm * 32 + mt * 16 + (lane >> 2) + half_i * 8;
            if (r >= M) continue;
#pragma unroll
            for (int nt = 0; nt < 8; nt++) {
                int cidx = col0 + wn * 64 + nt * 8 + (lane & 3) * 2;
                float v0 = acc[mt][nt][half_i * 2 + 0] + bias[cidx];
                float v1 = acc[mt][nt][half_i * 2 + 1] + bias[cidx + 1];
                if (relu) { v0 = fmaxf(v0, 0.f); v1 = fmaxf(v1, 0.f); }
                if (write_half) {
                    __half2 hv;
                    hv.x = __float2half_rn(v0);
                    hv.y = __float2half_rn(v1);
                    *reinterpret_cast<__half2*>(outh + (size_t)r * ostride + (cidx - coff)) = hv;
                } else {
                    float2 o = make_float2(v0, v1);
                    *reinterpret_cast<float2*>(outf + (size_t)r * ostride + (cidx - coff)) = o;
                }
            }
        }
    }
#undef LOAD_STAGE
}

// ---------------- GEMM + residual(fp16) + LayerNorm fused (N = 256) --------
// tile 128x256, 512 threads (4 wm x 4 wn warps, warp tile 32x64).
// t = resid + A@B^T + bias ; out = LN(t)*g + beta.
// out (fp32) and outh (fp16) each optional.
#define A_ST (128 * PADS * 2)
#define B_ST (256 * PADS * 2)
#define GEMMLN_SMEM (NSTAGE * (A_ST + B_ST))   // 122880 bytes

__global__ __launch_bounds__(512, 1)
void gemm_ln(const __half* __restrict__ A, int lda,
             const __half* __restrict__ B,
             const float* __restrict__ bias,
             const __half* __restrict__ resid,
             const float* __restrict__ lng, const float* __restrict__ lnb,
             float* __restrict__ out, __half* __restrict__ outh,
             int M, int K)
{
    extern __shared__ __align__(16) __half dynsmem[];

    const int tid  = threadIdx.x;
    const int wid  = tid >> 5;
    const int lane = tid & 31;
    const int wm   = wid & 3;
    const int wn   = wid >> 2;
    const int row0 = blockIdx.y * 128;

    const uint32_t sbase = smem_u32(dynsmem);
    const uint32_t sbB = sbase + NSTAGE * A_ST;
    const int NC2 = K >> 6;

    float acc[2][8][4];
#pragma unroll
    for (int i = 0; i < 2; i++)
#pragma unroll
        for (int j = 0; j < 8; j++)
#pragma unroll
            for (int t = 0; t < 4; t++) acc[i][j][t] = 0.f;

#define LOAD_STAGE_LN(buf, cc) do {                                           \
        int _kc = (cc) << 5;                                                  \
        uint32_t _dA = sbase + (buf) * A_ST;                                  \
        uint32_t _dB = sbB + (buf) * B_ST;                                    \
        {                                                                     \
            int _r = tid >> 2, _k8 = tid & 3;                                 \
            int _gr = row0 + _r; if (_gr >= M) _gr = M - 1;                   \
            CP_ASYNC16(_dA + (_r * PADS + _k8 * 8) * 2,                       \
                       A + (size_t)_gr * lda + _kc + _k8 * 8);                \
        }                                                                     \
        _Pragma("unroll")                                                     \
        for (int _i = 0; _i < 2; ++_i) {                                      \
            int _c = tid + _i * 512;                                          \
            int _r = _c >> 2, _k8 = _c & 3;                                   \
            CP_ASYNC16(_dB + (_r * PADS + _k8 * 8) * 2,                       \
                       B + (size_t)_r * K + _kc + _k8 * 8);                   \
        }                                                                     \
    } while (0)

    LOAD_STAGE_LN(0, 0);
    LOAD_STAGE_LN(1, 1);
    CP_COMMIT();

    for (int c = 0; c < NC2; ++c) {
        CP_WAIT(0);
        __syncthreads();

        if (c + 1 < NC2) {
            const int pb = ((c + 1) & 1) << 1;
            LOAD_STAGE_LN(pb, 2 * (c + 1));
            LOAD_STAGE_LN(pb + 1, 2 * (c + 1) + 1);
        }
        CP_COMMIT();

        const int cb = (c & 1) << 1;
#pragma unroll
        for (int hs = 0; hs < 2; hs++) {
            const uint32_t baseA = sbase + (cb + hs) * A_ST;
            const uint32_t baseB = sbB + (cb + hs) * B_ST;
#pragma unroll
            for (int kk = 0; kk < 32; kk += 16) {
                uint32_t a[2][4];
#pragma unroll
                for (int mt = 0; mt < 2; mt++) {
                    int r = wm * 32 + mt * 16 + (lane & 15);
                    int kc = kk + ((lane & 16) ? 8 : 0);
                    ldmatrix_x4(a[mt][0], a[mt][1], a[mt][2], a[mt][3],
                                baseA + (r * PADS + kc) * 2);
                }
                uint32_t b[8][2];
#pragma unroll
                for (int np = 0; np < 4; np++) {
                    int n = wn * 64 + np * 16 + (lane & 7) + ((lane & 16) ? 8 : 0);
                    int kc = kk + ((lane & 8) ? 8 : 0);
                    ldmatrix_x4(b[2 * np][0], b[2 * np][1], b[2 * np + 1][0], b[2 * np + 1][1],
                                baseB + (n * PADS + kc) * 2);
                }
#pragma unroll
                for (int mt = 0; mt < 2; mt++)
#pragma unroll
                    for (int nt = 0; nt < 8; nt++)
                        mma_f16(acc[mt][nt], a[mt], b[nt]);
            }
        }
    }

    // ---- fused epilogue: bias + fp16 residual + per-row LayerNorm ----
    __syncthreads();
    float* red = reinterpret_cast<float*>(dynsmem);   // [4 wn][128 rows][2]

#pragma unroll
    for (int mt = 0; mt < 2; mt++) {
#pragma unroll
        for (int hf = 0; hf < 2; hf++) {
            int lr = wm * 32 + mt * 16 + (lane >> 2) + hf * 8;
            int r = row0 + lr;
            int rc = (r < M) ? r : (M - 1);
            float s1 = 0.f, s2 = 0.f;
#pragma unroll
            for (int nt = 0; nt < 8; nt++) {
                int cidx = wn * 64 + nt * 8 + (lane & 3) * 2;
                __half2 rh = *reinterpret_cast<const __half2*>(resid + (size_t)rc * 256 + cidx);
                float2 res = __half22float2(rh);
                float2 bv = *reinterpret_cast<const float2*>(bias + cidx);
                float v0 = acc[mt][nt][hf * 2 + 0] + bv.x + res.x;
                float v1 = acc[mt][nt][hf * 2 + 1] + bv.y + res.y;
                acc[mt][nt][hf * 2 + 0] = v0;
                acc[mt][nt][hf * 2 + 1] = v1;
                s1 += v0 + v1;
                s2 += v0 * v0 + v1 * v1;
            }
            s1 += __shfl_xor_sync(0xffffffffu, s1, 1);
            s2 += __shfl_xor_sync(0xffffffffu, s2, 1);
            s1 += __shfl_xor_sync(0xffffffffu, s1, 2);
            s2 += __shfl_xor_sync(0xffffffffu, s2, 2);
            if ((lane & 3) == 0) {
                red[(wn * 128 + lr) * 2 + 0] = s1;
                red[(wn * 128 + lr) * 2 + 1] = s2;
            }
        }
    }
    __syncthreads();

#pragma unroll
    for (int mt = 0; mt < 2; mt++) {
#pragma unroll
        for (int hf = 0; hf < 2; hf++) {
            int lr = wm * 32 + mt * 16 + (lane >> 2) + hf * 8;
            int r = row0 + lr;
            if (r >= M) continue;
            float t1 = red[(0 * 128 + lr) * 2 + 0] + red[(1 * 128 + lr) * 2 + 0]
                     + red[(2 * 128 + lr) * 2 + 0] + red[(3 * 128 + lr) * 2 + 0];
            float t2 = red[(0 * 128 + lr) * 2 + 1] + red[(1 * 128 + lr) * 2 + 1]
                     + red[(2 * 128 + lr) * 2 + 1] + red[(3 * 128 + lr) * 2 + 1];
            float mean = t1 * (1.f / 256.f);
            float var = t2 * (1.f / 256.f) - mean * mean;
            float inv = rsqrtf(var + 1e-5f);
#pragma unroll
            for (int nt = 0; nt < 8; nt++) {
                int cidx = wn * 64 + nt * 8 + (lane & 3) * 2;
                float2 gv = *reinterpret_cast<const float2*>(lng + cidx);
                float2 bv = *reinterpret_cast<const float2*>(lnb + cidx);
                float o0 = (acc[mt][nt][hf * 2 + 0] - mean) * inv * gv.x + bv.x;
                float o1 = (acc[mt][nt][hf * 2 + 1] - mean) * inv * gv.y + bv.y;
                if (out)
                    *reinterpret_cast<float2*>(out + (size_t)r * 256 + cidx) = make_float2(o0, o1);
                if (outh) {
                    __half2 hv;
                    hv.x = __float2half_rn(o0);
                    hv.y = __float2half_rn(o1);
                    *reinterpret_cast<__half2*>(outh + (size_t)r * 256 + cidx) = hv;
                }
            }
        }
    }
#undef LOAD_STAGE_LN
}

// ---------------- fused weight prep + qh = fp16(src + pos) -----------------
__device__ __forceinline__ void wtr1(const float* __restrict__ W, __half* __restrict__ Wt,
                                     int K_, int N_, int i)
{
    int k = i / N_, n = i % N_;
    Wt[(size_t)n * K_ + k] = __float2half_rn(W[i]);
}

#define PREP_ITEMS 754304
#define ADD_ITEMS  (MTOK * DMODEL / 4)
#define PA_TOTAL   (PREP_ITEMS + ADD_ITEMS)

__global__ void prep_add_kernel(const float* __restrict__ vW, const float* __restrict__ oW,
                                const float* __restrict__ aW, const float* __restrict__ uW,
                                const float* __restrict__ f1W, const float* __restrict__ f2W,
                                const float* __restrict__ vb, const float* __restrict__ ob,
                                const float* __restrict__ ab,
                                __half* __restrict__ wtp, __half* __restrict__ wtu,
                                __half* __restrict__ wtf1, __half* __restrict__ wtf2,
                                float* __restrict__ biasp,
                                const float* __restrict__ srca, const float* __restrict__ posb,
                                __half* __restrict__ qh)
{
    int i = blockIdx.x * blockDim.x + threadIdx.x;
    if (i >= PREP_ITEMS) {
        int t = i - PREP_ITEMS;
        if (t >= ADD_ITEMS) return;
        float4 x = reinterpret_cast<const float4*>(srca)[t];
        float4 y = reinterpret_cast<const float4*>(posb)[t];
        x.x += y.x; x.y += y.y; x.z += y.z; x.w += y.w;
        __half2 h0 = __floats2half2_rn(x.x, x.y);
        __half2 h1 = __floats2half2_rn(x.z, x.w);
        uint2 hp;
        hp.x = *reinterpret_cast<uint32_t*>(&h0);
        hp.y = *reinterpret_cast<uint32_t*>(&h1);
        reinterpret_cast<uint2*>(qh)[t] = hp;
        return;
    }
    if (i < 65536)       { wtr1(vW, wtp, 256, 256, i); return; }
    i -= 65536;
    if (i < 65536)       { wtr1(oW, wtp + 256 * 256, 256, 256, i); return; }
    i -= 65536;
    if (i < 32768)       { wtr1(aW, wtp + 512 * 256, 256, 128, i); return; }
    i -= 32768;
    if (i < 65536)       { wtr1(uW, wtu, 256, 256, i); return; }
    i -= 65536;
    if (i < 262144)      { wtr1(f1W, wtf1, 256, 1024, i); return; }
    i -= 262144;
    if (i < 262144)      { wtr1(f2W, wtf2, 1024, 256, i); return; }
    i -= 262144;
    if (i < 256)         { biasp[i] = vb[i]; return; }
    if (i < 512)         { biasp[i] = ob[i - 256]; return; }
    if (i < 640)         { biasp[i] = ab[i - 512]; return; }
}

// ---------------- MSDA: fused softmax + float4 gathers (row-major value) ---
__global__ __launch_bounds__(256)
void msda_kernel(const __half* __restrict__ value, const float* __restrict__ offs,
                 const float* __restrict__ aw, const float* __restrict__ ref,
                 const int* __restrict__ shapes, const int* __restrict__ starts,
                 __half* __restrict__ outh)
{
    const int tok = blockIdx.x;
    const int h = threadIdx.x >> 5;
    const int lane = threadIdx.x & 31;
    const int j = lane & 15;
    const int b = tok / LIN;
    const int l = j >> 2;

    const int Hl = shapes[l * 2 + 0];
    const int Wl = shapes[l * 2 + 1];
    const int st = starts[l];
    const float fW = (float)Wl, fH = (float)Hl;
    const float rx = ref[(size_t)tok * 8 + l * 2 + 0];
    const float ry = ref[(size_t)tok * 8 + l * 2 + 1];
    const float2 off = *reinterpret_cast<const float2*>(offs + (size_t)tok * 256 + h * 32 + 2 * j);

    float logit = aw[(size_t)tok * 128 + h * 16 + j];
    float m = logit;
#pragma unroll
    for (int o = 8; o; o >>= 1) m = fmaxf(m, __shfl_xor_sync(0xffffffffu, m, o, 16));
    float e = expf(logit - m);
    float s = e;
#pragma unroll
    for (int o = 8; o; o >>= 1) s += __shfl_xor_sync(0xffffffffu, s, o, 16);
    float wgt = e / s;

    float x = (rx + off.x / fW) * fW - 0.5f;
    float y = (ry + off.y / fH) * fH - 0.5f;
    float x0f = floorf(x), y0f = floorf(y);
    float dx = x - x0f, dy = y - y0f;
    int x0 = (int)x0f, y0 = (int)y0f;
    int x1 = x0 + 1, y1 = y0 + 1;

    bool xv0 = (x0 >= 0) & (x0 < Wl);
    bool xv1 = (x1 >= 0) & (x1 < Wl);
    bool yv0 = (y0 >= 0) & (y0 < Hl);
    bool yv1 = (y1 >= 0) & (y1 < Hl);

    float w00 = (xv0 && yv0) ? wgt * (1.f - dx) * (1.f - dy) : 0.f;
    float w10 = (xv1 && yv0) ? wgt * dx * (1.f - dy) : 0.f;
    float w01 = (xv0 && yv1) ? wgt * (1.f - dx) * dy : 0.f;
    float w11 = (xv1 && yv1) ? wgt * dx * dy : 0.f;

    int cx0 = min(max(x0, 0), Wl - 1), cx1 = min(max(x1, 0), Wl - 1);
    int cy0 = min(max(y0, 0), Hl - 1), cy1 = min(max(y1, 0), Hl - 1);
    const int base = b * LIN + st;
    int i00 = base + cy0 * Wl + cx0;
    int i10 = base + cy0 * Wl + cx1;
    int i01 = base + cy1 * Wl + cx0;
    int i11 = base + cy1 * Wl + cx1;

    const int g = lane >> 2;
    const int c4 = lane & 3;
    const __half* vch = value + h * DH + c4 * 8;
    float acc[8] = {0.f, 0.f, 0.f, 0.f, 0.f, 0.f, 0.f, 0.f};

#pragma unroll
    for (int p = 0; p < 2; p++) {
        const int pt = p * 8 + g;
        int a00 = __shfl_sync(0xffffffffu, i00, pt);
        int a10 = __shfl_sync(0xffffffffu, i10, pt);
        int a01 = __shfl_sync(0xffffffffu, i01, pt);
        int a11 = __shfl_sync(0xffffffffu, i11, pt);
        float u00 = __shfl_sync(0xffffffffu, w00, pt);
        float u10 = __shfl_sync(0xffffffffu, w10, pt);
        float u01 = __shfl_sync(0xffffffffu, w01, pt);
        float u11 = __shfl_sync(0xffffffffu, w11, pt);

        uint4 r00 = *reinterpret_cast<const uint4*>(vch + (size_t)a00 * DMODEL);
        uint4 r10 = *reinterpret_cast<const uint4*>(vch + (size_t)a10 * DMODEL);
        uint4 r01 = *reinterpret_cast<const uint4*>(vch + (size_t)a01 * DMODEL);
        uint4 r11 = *reinterpret_cast<const uint4*>(vch + (size_t)a11 * DMODEL);

#define ACC8(rv, u) do {                                                      \
        const __half2* _h = reinterpret_cast<const __half2*>(&(rv));          \
        _Pragma("unroll")                                                     \
        for (int _k = 0; _k < 4; _k++) {                                      \
            float2 _f = __half22float2(_h[_k]);                               \
            acc[2 * _k + 0] = fmaf(u, _f.x, acc[2 * _k + 0]);                 \
            acc[2 * _k + 1] = fmaf(u, _f.y, acc[2 * _k + 1]);                 \
        } } while (0)

        ACC8(r00, u00);
        ACC8(r10, u10);
        ACC8(r01, u01);
        ACC8(r11, u11);
#undef ACC8
    }

#pragma unroll
    for (int o = 4; o <= 16; o <<= 1) {
#pragma unroll
        for (int k = 0; k < 8; k++)
            acc[k] += __shfl_xor_sync(0xffffffffu, acc[k], o);
    }

    if (lane < 4) {
        __half2 h0 = __floats2half2_rn(acc[0], acc[1]);
        __half2 h1 = __floats2half2_rn(acc[2], acc[3]);
        __half2 h2 = __floats2half2_rn(acc[4], acc[5]);
        __half2 h3 = __floats2half2_rn(acc[6], acc[7]);
        uint4 o;
        o.x = *reinterpret_cast<uint32_t*>(&h0);
        o.y = *reinterpret_cast<uint32_t*>(&h1);
        o.z = *reinterpret_cast<uint32_t*>(&h2);
        o.w = *reinterpret_cast<uint32_t*>(&h3);
        *reinterpret_cast<uint4*>(outh + (size_t)tok * DMODEL + h * DH + lane * 8) = o;
    }
}

// ---------------- launch ----------------
extern "C" void kernel_launch(void* const* d_in, const int* in_sizes, int n_in,
                              void* d_out, int out_size)
{
    const float* src    = (const float*)d_in[0];
    const float* pos    = (const float*)d_in[1];
    const float* refpts = (const float*)d_in[2];
    const int*   shapes = (const int*)  d_in[3];
    const int*   starts = (const int*)  d_in[4];
    const float* value_w = (const float*)d_in[5];
    const float* value_b = (const float*)d_in[6];
    const float* offs_w  = (const float*)d_in[7];
    const float* offs_b  = (const float*)d_in[8];
    const float* attn_w  = (const float*)d_in[9];
    const float* attn_b  = (const float*)d_in[10];
    const float* out_w   = (const float*)d_in[11];
    const float* out_b   = (const float*)d_in[12];
    const float* ln1_g   = (const float*)d_in[13];
    const float* ln1_b   = (const float*)d_in[14];
    const float* ff1_w   = (const float*)d_in[15];
    const float* ff1_b   = (const float*)d_in[16];
    const float* ff2_w   = (const float*)d_in[17];
    const float* ff2_b   = (const float*)d_in[18];
    const float* ln2_g   = (const float*)d_in[19];
    const float* ln2_b   = (const float*)d_in[20];
    float* outp = (float*)d_out;

    float *offs, *aw, *biasp;
    __half *qh, *value, *msdah, *xh, *ffh;
    __half *wtp, *wtu, *wtf1, *wtf2;
    cudaGetSymbolAddress((void**)&qh,    g_qh);
    cudaGetSymbolAddress((void**)&value, g_value);
    cudaGetSymbolAddress((void**)&offs,  g_offs);
    cudaGetSymbolAddress((void**)&aw,    g_aw);
    cudaGetSymbolAddress((void**)&msdah, g_msdah);
    cudaGetSymbolAddress((void**)&xh,    g_xh);
    cudaGetSymbolAddress((void**)&ffh,   g_ffh);
    cudaGetSymbolAddress((void**)&wtp,   g_wt_proj);
    cudaGetSymbolAddress((void**)&wtu,   g_wt_out);
    cudaGetSymbolAddress((void**)&wtf1,  g_wt_ff1);
    cudaGetSymbolAddress((void**)&wtf2,  g_wt_ff2);
    cudaGetSymbolAddress((void**)&biasp, g_bias_proj);

    cudaFuncSetAttribute(gemm_mma, cudaFuncAttributeMaxDynamicSharedMemorySize, GEMM_SMEM);
    cudaFuncSetAttribute(gemm_ln, cudaFuncAttributeMaxDynamicSharedMemorySize, GEMMLN_SMEM);

    const int M = MTOK;
    const int gy = (M + 127) / 128;

    // 0. fused weight prep + qh = fp16(src + pos)
    prep_add_kernel<<<(PA_TOTAL + 255) / 256, 256>>>(value_w, offs_w, attn_w, out_w, ff1_w, ff2_w,
                                                     value_b, offs_b, attn_b,
                                                     wtp, wtu, wtf1, wtf2, biasp,
                                                     src, pos, qh);

    // 1. fused projections: [value(fp16) | offs | aw] = qh @ Wp^T
    gemm_mma<<<dim3(5, gy), 256, GEMM_SMEM>>>(qh, 256, wtp, 256, biasp,
                                              nullptr, value, offs, aw, M, 256, 640, 0, 2);

    // 2. deformable sampling with fused softmax
    msda_kernel<<<M, 256>>>(value, offs, aw, refpts, shapes, starts, msdah);

    // 3. xh = fp16(LN(qh + msda @ out_w + out_b))   [fused GEMM+LN]
    gemm_ln<<<dim3(1, gy), 512, GEMMLN_SMEM>>>(msdah, 256, wtu, out_b,
                                               qh, ln1_g, ln1_b, nullptr, xh, M, 256);

    // 4. ffh = relu(xh @ ff1_w + ff1_b) -> fp16
    gemm_mma<<<dim3(8, gy), 256, GEMM_SMEM>>>(xh, 256, wtf1, 256, ff1_b,
                                              nullptr, ffh, nullptr, nullptr, M, 256, 1024, 1, 1);

    // 5. out = LN(xh + ffh @ ff2_w + ff2_b)   [fused GEMM+LN]
    gemm_ln<<<dim3(1, gy), 512, GEMMLN_SMEM>>>(ffh, 1024, wtf2, ff2_b,
                                               xh, ln2_g, ln2_b, outp, nullptr, M, 1024);
}